// round 14
// baseline (speedup 1.0000x reference)
#include <cuda_runtime.h>
#include <cuda_bf16.h>
#include <math.h>
#include <stdint.h>

#define NTYPES 2
#define NETYPES 2
#define NN 50000
#define FINDIM 128
#define HIDDIM 128
#define NH 4
#define DH 32
#define NL 2
#define NEDGE 400000
#define MTILES 3125   // NN / 16 exactly

__device__ __constant__ int c_esrc[2] = {0, 1};
__device__ __constant__ int c_edst[2] = {1, 0};

// ---- scratch (__device__ globals; no allocation allowed) ----
__device__ float g_proj[(size_t)NTYPES * NN * 384];
__device__ float g_wcat[(size_t)NTYPES * 128 * 384];
__device__ float g_bcat[NL][NTYPES * 384];
// B fragment image slots: lin:0-1 | wcat0:2-7 | aw0:8-9 | wcat1:10-15 | aw1:16-17
__device__ uint8_t g_bsplit[(size_t)18 * 65536];
__device__ uint4 g_pkA_hi[(size_t)NTYPES * MTILES * 8 * 32];   // x / gelu(agg) images
__device__ uint4 g_pkA_lo[(size_t)NTYPES * MTILES * 8 * 32];
__device__ uint4 g_pkH_hi[(size_t)NTYPES * MTILES * 8 * 32];   // h images
__device__ uint4 g_pkH_lo[(size_t)NTYPES * MTILES * 8 * 32];
__device__ int   g_deg[NETYPES * NN];
__device__ int   g_off[NETYPES * (NN + 1)];
__device__ int   g_cur[NETYPES * NN];
__device__ int   g_srcs[(size_t)NETYPES * NEDGE];
__device__ int   g_last[NTYPES * NN];

__device__ __forceinline__ float gelu_exact(float x) {
    return 0.5f * x * (1.0f + erff(x * 0.7071067811865476f));
}

// split x,y into bf16 hi pair (packed b16x2, x in low half) + lo pair
__device__ __forceinline__ uint32_t split2(float x, float y, uint32_t& lo) {
    __nv_bfloat16 hx = __float2bfloat16(x), hy = __float2bfloat16(y);
    float rx = x - __bfloat162float(hx);
    float ry = y - __bfloat162float(hy);
    __nv_bfloat16 lx = __float2bfloat16(rx), ly = __float2bfloat16(ry);
    uint16_t uhx = *(uint16_t*)&hx, uhy = *(uint16_t*)&hy;
    uint16_t ulx = *(uint16_t*)&lx, uly = *(uint16_t*)&ly;
    lo = ((uint32_t)uly << 16) | ulx;
    return ((uint32_t)uhy << 16) | uhx;
}
// reconstruct fp32 pair from hi/lo packed bf16x2
__device__ __forceinline__ float2 unsplit2(uint32_t h, uint32_t l) {
    __nv_bfloat162 hb = *(__nv_bfloat162*)&h;
    __nv_bfloat162 lb = *(__nv_bfloat162*)&l;
    float2 r;
    r.x = __low2float(hb) + __low2float(lb);
    r.y = __high2float(hb) + __high2float(lb);
    return r;
}

#define MMA_BF16(d, a, b0, b1) \
    asm volatile("mma.sync.aligned.m16n8k16.row.col.f32.bf16.bf16.f32 " \
                 "{%0,%1,%2,%3},{%4,%5,%6,%7},{%8,%9},{%0,%1,%2,%3};" \
                 : "+f"((d)[0]), "+f"((d)[1]), "+f"((d)[2]), "+f"((d)[3]) \
                 : "r"((a).x), "r"((a).y), "r"((a).z), "r"((a).w), "r"(b0), "r"(b1))

// ---------------- init ----------------
__global__ void init_kernel() {
    int idx = blockIdx.x * blockDim.x + threadIdx.x;
    if (idx < NETYPES * NN) g_deg[idx] = 0;
    if (idx < NTYPES * NN)  g_last[idx] = -1;
}

// ---------------- CSR build ----------------
__global__ void edge_count_kernel(const int* __restrict__ ei) {
    int idx = blockIdx.x * blockDim.x + threadIdx.x;
    if (idx >= NETYPES * NEDGE) return;
    int e = idx / NEDGE, j = idx % NEDGE;
    const int* base = ei + (size_t)e * 2 * NEDGE;
    int src = base[j];
    int dst = base[NEDGE + j];
    atomicAdd(&g_deg[e * NN + dst], 1);
    atomicMax(&g_last[c_esrc[e] * NN + src], j);
}

__global__ void scan_kernel() {
    int e = blockIdx.x;
    __shared__ int sh[1024];
    int tidx = threadIdx.x;
    const int CH = (NN + 1023) / 1024;
    int base = tidx * CH;
    int s = 0;
    for (int i = 0; i < CH; i++) { int id = base + i; if (id < NN) s += g_deg[e * NN + id]; }
    sh[tidx] = s;
    __syncthreads();
    for (int o = 1; o < 1024; o <<= 1) {
        int v = (tidx >= o) ? sh[tidx - o] : 0;
        __syncthreads();
        sh[tidx] += v;
        __syncthreads();
    }
    int run = sh[tidx] - s;
    for (int i = 0; i < CH; i++) {
        int id = base + i;
        if (id < NN) {
            g_off[e * (NN + 1) + id] = run;
            g_cur[e * NN + id] = run;
            run += g_deg[e * NN + id];
        }
    }
    if (tidx == 1023) g_off[e * (NN + 1) + NN] = sh[1023];
}

__global__ void edge_scatter_kernel(const int* __restrict__ ei) {
    int idx = blockIdx.x * blockDim.x + threadIdx.x;
    if (idx >= NETYPES * NEDGE) return;
    int e = idx / NEDGE, j = idx % NEDGE;
    const int* base = ei + (size_t)e * 2 * NEDGE;
    int src = base[j];
    int dst = base[NEDGE + j];
    int pos = atomicAdd(&g_cur[e * NN + dst], 1);
    g_srcs[(size_t)e * NEDGE + pos] = src;
}

// ---------------- compose Wcat = [q_w | k_w@R_att | v_w@R_msg] ----------------
__global__ void compose_kernel(const float* __restrict__ kw, const float* __restrict__ kb,
                               const float* __restrict__ qw, const float* __restrict__ qb,
                               const float* __restrict__ vw, const float* __restrict__ vb,
                               const float* __restrict__ ratt, const float* __restrict__ rmsg,
                               int l) {
    int idx = blockIdx.x * blockDim.x + threadIdx.x;
    const int total = NTYPES * 384 * 129;
    if (idx >= total) return;
    int t = idx / (384 * 129);
    int r = idx % (384 * 129);
    int j = r / 129;
    int i = r % 129;
    float val;
    if (j < 128) {
        val = (i < 128) ? qw[(((size_t)l * NTYPES + t) * 128 + i) * 128 + j]
                        : qb[((size_t)l * NTYPES + t) * 128 + j];
    } else {
        bool isK = (j < 256);
        int jo = j - (isK ? 128 : 256);
        int hh = jo >> 5, eo = jo & 31;
        int e = 0;
        for (int ee = 0; ee < NETYPES; ee++) if (c_esrc[ee] == t) e = ee;
        const float* rel = (isK ? ratt : rmsg) +
                           ((((size_t)l * NETYPES + e) * NH + hh) * DH) * DH + eo;
        float s = 0.f;
        if (i < 128) {
            const float* wr = (isK ? kw : vw) + (((size_t)l * NTYPES + t) * 128 + i) * 128 + hh * 32;
            #pragma unroll
            for (int d = 0; d < 32; d++) s += wr[d] * rel[d * 32];
        } else {
            const float* br = (isK ? kb : vb) + ((size_t)l * NTYPES + t) * 128 + hh * 32;
            #pragma unroll
            for (int d = 0; d < 32; d++) s += br[d] * rel[d * 32];
        }
        val = s;
    }
    if (i < 128) g_wcat[((size_t)t * 128 + i) * 384 + j] = val;
    else         g_bcat[l][t * 384 + j] = val;
}

// ---------------- A split+pack: fp32 [z][NN][128] -> mma A-fragment images ----------------
__global__ void split_pack_kernel(const float* __restrict__ src,
                                  uint4* __restrict__ dhi, uint4* __restrict__ dlo) {
    int idx = blockIdx.x * blockDim.x + threadIdx.x;
    const int total = NTYPES * MTILES * 8 * 32;
    if (idx >= total) return;
    int lane = idx & 31;
    int s = (idx >> 5) & 7;
    int mt = (idx >> 8) % MTILES;
    int z = idx / (MTILES * 8 * 32);
    int g = lane >> 2, tig = lane & 3;
    int r0 = mt * 16 + g;
    int c0 = s * 16 + tig * 2;
    const float* S = src + (size_t)z * NN * 128;
    float2 p00 = *(const float2*)(S + (size_t)r0 * 128 + c0);
    float2 p10 = *(const float2*)(S + (size_t)(r0 + 8) * 128 + c0);
    float2 p01 = *(const float2*)(S + (size_t)r0 * 128 + c0 + 8);
    float2 p11 = *(const float2*)(S + (size_t)(r0 + 8) * 128 + c0 + 8);
    uint4 hi, lo;
    hi.x = split2(p00.x, p00.y, lo.x);
    hi.y = split2(p10.x, p10.y, lo.y);
    hi.z = split2(p01.x, p01.y, lo.z);
    hi.w = split2(p11.x, p11.y, lo.w);
    size_t o = (((size_t)z * MTILES + mt) * 8 + s) * 32 + lane;
    dhi[o] = hi;
    dlo[o] = lo;
}

// ---------------- B prep: fp32 W[k][n] -> mma B-fragment images ----------------
__global__ void prep_b_kernel(const float* __restrict__ Wsrc, int Nout, int zstride, int imgBase) {
    int idx = blockIdx.x * blockDim.x + threadIdx.x;
    const int ntl = Nout >> 7;
    const int total = NTYPES * ntl * 8 * 16 * 32;
    if (idx >= total) return;
    int lane = idx & 31;
    int f = (idx >> 5) & 15;
    int s = (idx >> 9) & 7;
    int nt = (idx >> 12) % ntl;
    int z = idx / (ntl * 8 * 16 * 32);
    int g = lane >> 2, tig = lane & 3;
    int n = nt * 128 + f * 8 + g;
    int k0 = s * 16 + tig * 2;
    const float* W = Wsrc + (size_t)z * zstride;
    float w00 = W[(size_t)k0 * Nout + n];
    float w01 = W[(size_t)(k0 + 1) * Nout + n];
    float w10 = W[(size_t)(k0 + 8) * Nout + n];
    float w11 = W[(size_t)(k0 + 9) * Nout + n];
    uint4 q;
    q.x = split2(w00, w01, q.z);
    q.y = split2(w10, w11, q.w);
    uint4* img = (uint4*)(g_bsplit + ((size_t)(imgBase + z * ntl + nt)) * 65536);
    img[(s * 16 + f) * 32 + lane] = q;
}

// ---------------- bf16 3-term mma GEMM, N=64 per CTA (high occupancy) ----------------
// gridDim.y = 2 * ntl; each CTA does one 64-col half of a 128-wide B image.
// epi: 0 none, 1 relu + edge-weight row scaling, 2 skip-gated residual (resid from packed images).
// C may be nullptr (pack-only output). z = zoff + blockIdx.z.
__global__ void __launch_bounds__(256, 3)
gemm_mma(const uint4* __restrict__ Ahi, const uint4* __restrict__ Alo,
         const float* __restrict__ bias, int sB,
         float* C, size_t sC,
         const uint4* resHi, const uint4* resLo,
         const float* __restrict__ skipv,
         int Ntot, int epi, const float* __restrict__ ew,
         uint4* packHi, uint4* packLo, int imgBase, int zoff) {
    extern __shared__ uint4 Bs[];  // 2048 x 16B = 32KB
    const int z = zoff + blockIdx.z;
    const int nt = blockIdx.y >> 1, half = blockIdx.y & 1;
    const int tid = threadIdx.x, warp = tid >> 5, lane = tid & 31;
    const int g = lane >> 2, tig = lane & 3;
    const int ntl = gridDim.y >> 1;

    {
        const uint4* Bimg = (const uint4*)(g_bsplit + ((size_t)(imgBase + z * ntl + nt)) * 65536);
        #pragma unroll
        for (int i = 0; i < 8; i++) {
            int j = tid + i * 256;
            int s = j >> 8;
            Bs[j] = Bimg[(s << 9) + (half << 8) + (j & 255)];
        }
    }
    __syncthreads();

    const int mtg = blockIdx.x * 8 + warp;   // one 16-row m-tile per warp
    float acc[8][4];
    #pragma unroll
    for (int b = 0; b < 8; b++)
        #pragma unroll
        for (int c = 0; c < 4; c++) acc[b][c] = 0.f;

    const bool valid = (mtg < MTILES);
    uint4 aH, aL, nH, nL;
    const uint4 zero4 = make_uint4(0, 0, 0, 0);
    if (valid) {
        size_t o = (((size_t)z * MTILES + mtg) * 8 + 0) * 32 + lane;
        aH = Ahi[o]; aL = Alo[o];
    } else { aH = zero4; aL = zero4; }

    for (int s = 0; s < 8; s++) {
        if (s < 7) {
            if (valid) {
                size_t o = (((size_t)z * MTILES + mtg) * 8 + (s + 1)) * 32 + lane;
                nH = Ahi[o]; nL = Alo[o];
            } else { nH = zero4; nL = zero4; }
        }
        #pragma unroll
        for (int f = 0; f < 8; f++) {
            uint4 q = Bs[s * 256 + f * 32 + lane];
            MMA_BF16(acc[f], aH, q.x, q.y);   // ah*bh
            MMA_BF16(acc[f], aH, q.z, q.w);   // ah*bl
            MMA_BF16(acc[f], aL, q.x, q.y);   // al*bh
        }
        aH = nH; aL = nL;
    }

    // ---- epilogue ----
    if (!valid) return;
    const float* biasz = bias + (size_t)z * sB;
    float* Cz = C ? C + (size_t)z * sC : nullptr;
    float beta = 1.f, omb = 0.f;
    if (epi == 2) {
        float sv = skipv[z];
        beta = 1.f / (1.f + expf(-sv));
        omb = 1.f - beta;
    }
    const int n0 = nt * 128 + half * 64;
    int r0 = mtg * 16 + g;
    float w0 = 1.f, w1 = 1.f;
    if (epi == 1) {
        int li0 = g_last[z * NN + r0];
        int li1 = g_last[z * NN + r0 + 8];
        if (li0 >= 0) w0 = 1.f / (1.f + expf(-ew[(size_t)z * NEDGE + li0]));
        if (li1 >= 0) w1 = 1.f / (1.f + expf(-ew[(size_t)z * NEDGE + li1]));
    }
    #pragma unroll
    for (int sl = 0; sl < 4; sl++) {
        int fe = sl * 2, fo = fe + 1;
        size_t o = (((size_t)z * MTILES + mtg) * 8 + (half * 4 + sl)) * 32 + lane;
        float ve[4], vo[4];
        {
            int c = n0 + fe * 8 + tig * 2;
            float2 b2 = *(const float2*)(biasz + c);
            ve[0] = acc[fe][0] + b2.x; ve[1] = acc[fe][1] + b2.y;
            ve[2] = acc[fe][2] + b2.x; ve[3] = acc[fe][3] + b2.y;
        }
        {
            int c = n0 + fo * 8 + tig * 2;
            float2 b2 = *(const float2*)(biasz + c);
            vo[0] = acc[fo][0] + b2.x; vo[1] = acc[fo][1] + b2.y;
            vo[2] = acc[fo][2] + b2.x; vo[3] = acc[fo][3] + b2.y;
        }
        if (epi == 1) {
            #pragma unroll
            for (int i = 0; i < 4; i++) { ve[i] = fmaxf(ve[i], 0.f); vo[i] = fmaxf(vo[i], 0.f); }
            ve[0] *= w0; ve[1] *= w0; ve[2] *= w1; ve[3] *= w1;
            vo[0] *= w0; vo[1] *= w0; vo[2] *= w1; vo[3] *= w1;
        } else if (epi == 2) {
            uint4 rh = resHi[o], rl = resLo[o];
            float2 p0 = unsplit2(rh.x, rl.x);
            float2 p1 = unsplit2(rh.y, rl.y);
            float2 p2 = unsplit2(rh.z, rl.z);
            float2 p3 = unsplit2(rh.w, rl.w);
            ve[0] = beta * ve[0] + omb * p0.x; ve[1] = beta * ve[1] + omb * p0.y;
            ve[2] = beta * ve[2] + omb * p1.x; ve[3] = beta * ve[3] + omb * p1.y;
            vo[0] = beta * vo[0] + omb * p2.x; vo[1] = beta * vo[1] + omb * p2.y;
            vo[2] = beta * vo[2] + omb * p3.x; vo[3] = beta * vo[3] + omb * p3.y;
        }
        if (Cz) {
            int ce = n0 + fe * 8 + tig * 2, co = n0 + fo * 8 + tig * 2;
            *(float2*)(Cz + (size_t)r0 * Ntot + ce)       = make_float2(ve[0], ve[1]);
            *(float2*)(Cz + (size_t)(r0 + 8) * Ntot + ce) = make_float2(ve[2], ve[3]);
            *(float2*)(Cz + (size_t)r0 * Ntot + co)       = make_float2(vo[0], vo[1]);
            *(float2*)(Cz + (size_t)(r0 + 8) * Ntot + co) = make_float2(vo[2], vo[3]);
        }
        if (packHi) {
            uint4 hi, lo;
            hi.x = split2(ve[0], ve[1], lo.x);
            hi.y = split2(ve[2], ve[3], lo.y);
            hi.z = split2(vo[0], vo[1], lo.z);
            hi.w = split2(vo[2], vo[3], lo.w);
            packHi[o] = hi;
            packLo[o] = lo;
        }
    }
}

// ---------------- attention + aggregation + gelu + pack, one edge type per launch ----------------
__global__ void __launch_bounds__(512)
attn_pack_kernel(const float* __restrict__ relp, int e,
                 uint4* __restrict__ dhi, uint4* __restrict__ dlo) {
    __shared__ float sO[16][132];
    int tid = threadIdx.x;
    int warp = tid >> 5, lane = tid & 31;
    int mt = blockIdx.x;
    int n = mt * 16 + warp;
    int t = c_edst[e], s = c_esrc[e];
    const float* projT = g_proj + (size_t)t * NN * 384;
    const float* projS = g_proj + (size_t)s * NN * 384;
    const int* offE = g_off + e * (NN + 1);
    const int* srcE = g_srcs + (size_t)e * NEDGE;
    int hg = lane >> 3;
    float ascale = relp[e * NH + hg] * 0.17677669529663689f;
    float4 q4 = *(const float4*)(projT + (size_t)n * 384 + lane * 4);
    int beg = offE[n], end = offE[n + 1];
    float m = -3.0e38f, ssum = 0.f;
    float4 acc = make_float4(0.f, 0.f, 0.f, 0.f);
    int p2 = beg;
    for (; p2 + 2 <= end; p2 += 2) {
        int u0 = srcE[p2], u1 = srcE[p2 + 1];
        const float* rs0 = projS + (size_t)u0 * 384;
        const float* rs1 = projS + (size_t)u1 * 384;
        float4 k0 = *(const float4*)(rs0 + 128 + lane * 4);
        float4 v0 = *(const float4*)(rs0 + 256 + lane * 4);
        float4 k1 = *(const float4*)(rs1 + 128 + lane * 4);
        float4 v1 = *(const float4*)(rs1 + 256 + lane * 4);
        float d0 = q4.x * k0.x + q4.y * k0.y + q4.z * k0.z + q4.w * k0.w;
        float d1 = q4.x * k1.x + q4.y * k1.y + q4.z * k1.z + q4.w * k1.w;
        d0 += __shfl_xor_sync(0xffffffffu, d0, 1);
        d1 += __shfl_xor_sync(0xffffffffu, d1, 1);
        d0 += __shfl_xor_sync(0xffffffffu, d0, 2);
        d1 += __shfl_xor_sync(0xffffffffu, d1, 2);
        d0 += __shfl_xor_sync(0xffffffffu, d0, 4);
        d1 += __shfl_xor_sync(0xffffffffu, d1, 4);
        float a0 = d0 * ascale, a1 = d1 * ascale;
        float nm = fmaxf(m, fmaxf(a0, a1));
        float sc = __expf(m - nm);
        float pe0 = __expf(a0 - nm), pe1 = __expf(a1 - nm);
        ssum = ssum * sc + pe0 + pe1;
        acc.x = acc.x * sc + pe0 * v0.x + pe1 * v1.x;
        acc.y = acc.y * sc + pe0 * v0.y + pe1 * v1.y;
        acc.z = acc.z * sc + pe0 * v0.z + pe1 * v1.z;
        acc.w = acc.w * sc + pe0 * v0.w + pe1 * v1.w;
        m = nm;
    }
    for (; p2 < end; ++p2) {
        int u = srcE[p2];
        const float* rs = projS + (size_t)u * 384;
        float4 k4 = *(const float4*)(rs + 128 + lane * 4);
        float4 v4 = *(const float4*)(rs + 256 + lane * 4);
        float d = q4.x * k4.x + q4.y * k4.y + q4.z * k4.z + q4.w * k4.w;
        d += __shfl_xor_sync(0xffffffffu, d, 1);
        d += __shfl_xor_sync(0xffffffffu, d, 2);
        d += __shfl_xor_sync(0xffffffffu, d, 4);
        float a = d * ascale;
        float nm = fmaxf(m, a);
        float sc = __expf(m - nm), pe = __expf(a - nm);
        ssum = ssum * sc + pe;
        acc.x = acc.x * sc + pe * v4.x;
        acc.y = acc.y * sc + pe * v4.y;
        acc.z = acc.z * sc + pe * v4.z;
        acc.w = acc.w * sc + pe * v4.w;
        m = nm;
    }
    float inv = 1.f / (ssum + 1e-16f);
    int cb = lane * 4;
    sO[warp][cb + 0] = acc.x * inv;
    sO[warp][cb + 1] = acc.y * inv;
    sO[warp][cb + 2] = acc.z * inv;
    sO[warp][cb + 3] = acc.w * inv;
    __syncthreads();

    if (tid < 256) {
        int sstep = tid >> 5, ln = tid & 31;
        int g = ln >> 2, tig = ln & 3;
        int c0 = sstep * 16 + tig * 2;
        float p00x = gelu_exact(sO[g][c0]);
        float p00y = gelu_exact(sO[g][c0 + 1]);
        float p10x = gelu_exact(sO[g + 8][c0]);
        float p10y = gelu_exact(sO[g + 8][c0 + 1]);
        float p01x = gelu_exact(sO[g][c0 + 8]);
        float p01y = gelu_exact(sO[g][c0 + 9]);
        float p11x = gelu_exact(sO[g + 8][c0 + 8]);
        float p11y = gelu_exact(sO[g + 8][c0 + 9]);
        uint4 hi, lo;
        hi.x = split2(p00x, p00y, lo.x);
        hi.y = split2(p10x, p10y, lo.y);
        hi.z = split2(p01x, p01y, lo.z);
        hi.w = split2(p11x, p11y, lo.w);
        size_t o = (((size_t)t * MTILES + mt) * 8 + sstep) * 32 + ln;
        dhi[o] = hi;
        dlo[o] = lo;
    }
}

// ---------------- launch ----------------
extern "C" void kernel_launch(void* const* d_in, const int* in_sizes, int n_in,
                              void* d_out, int out_size) {
    const float* x       = (const float*)d_in[0];
    const int*   ei      = (const int*)  d_in[1];
    const float* ew      = (const float*)d_in[2];
    const float* lin_w   = (const float*)d_in[3];
    const float* lin_b   = (const float*)d_in[4];
    const float* k_w     = (const float*)d_in[5];
    const float* k_b     = (const float*)d_in[6];
    const float* q_w     = (const float*)d_in[7];
    const float* q_b     = (const float*)d_in[8];
    const float* v_w     = (const float*)d_in[9];
    const float* v_b     = (const float*)d_in[10];
    const float* a_w     = (const float*)d_in[11];
    const float* a_b     = (const float*)d_in[12];
    const float* skip    = (const float*)d_in[13];
    const float* rel_att = (const float*)d_in[14];
    const float* rel_msg = (const float*)d_in[15];
    const float* rel_p   = (const float*)d_in[16];
    float* out = (float*)d_out;

    float *pproj, *pwcat, *pbcat;
    uint4 *pAh, *pAl, *pHh, *pHl;
    cudaGetSymbolAddress((void**)&pproj, g_proj);
    cudaGetSymbolAddress((void**)&pwcat, g_wcat);
    cudaGetSymbolAddress((void**)&pbcat, g_bcat);
    cudaGetSymbolAddress((void**)&pAh,   g_pkA_hi);
    cudaGetSymbolAddress((void**)&pAl,   g_pkA_lo);
    cudaGetSymbolAddress((void**)&pHh,   g_pkH_hi);
    cudaGetSymbolAddress((void**)&pHl,   g_pkH_lo);

    static int inited = 0;
    static cudaStream_t s2, s3;
    static cudaEvent_t evFork, evA, evB, evCnt, evCSR, evAt0, evOut1;
    const int SMEM_GEMM = 32768;
    if (!inited) {
        cudaFuncSetAttribute(gemm_mma, cudaFuncAttributeMaxDynamicSharedMemorySize, SMEM_GEMM);
        cudaStreamCreateWithFlags(&s2, cudaStreamNonBlocking);
        cudaStreamCreateWithFlags(&s3, cudaStreamNonBlocking);
        cudaEventCreateWithFlags(&evFork, cudaEventDisableTiming);
        cudaEventCreateWithFlags(&evA, cudaEventDisableTiming);
        cudaEventCreateWithFlags(&evB, cudaEventDisableTiming);
        cudaEventCreateWithFlags(&evCnt, cudaEventDisableTiming);
        cudaEventCreateWithFlags(&evCSR, cudaEventDisableTiming);
        cudaEventCreateWithFlags(&evAt0, cudaEventDisableTiming);
        cudaEventCreateWithFlags(&evOut1, cudaEventDisableTiming);
        inited = 1;
    }

    const int MB = (NN + 127) / 128;  // 391
    const int PACK_T = NTYPES * MTILES * 8 * 32;

    // ---- fork: weight-side prep on s2, CSR on main / s3 ----
    cudaEventRecord(evFork, 0);
    cudaStreamWaitEvent(s2, evFork, 0);

    // s2: independent prep chain
    split_pack_kernel<<<(PACK_T + 255) / 256, 256, 0, s2>>>(x, pAh, pAl);
    prep_b_kernel<<<(NTYPES * 4096 + 255) / 256, 256, 0, s2>>>(lin_w, 128, 128 * 128, 0);
    cudaEventRecord(evA, s2);
    compose_kernel<<<(NTYPES * 384 * 129 + 255) / 256, 256, 0, s2>>>(
        k_w, k_b, q_w, q_b, v_w, v_b, rel_att, rel_msg, 0);
    prep_b_kernel<<<(NTYPES * 3 * 4096 + 255) / 256, 256, 0, s2>>>(pwcat, 384, 128 * 384, 2);
    prep_b_kernel<<<(NTYPES * 4096 + 255) / 256, 256, 0, s2>>>(a_w, 128, 128 * 128, 8);
    compose_kernel<<<(NTYPES * 384 * 129 + 255) / 256, 256, 0, s2>>>(
        k_w, k_b, q_w, q_b, v_w, v_b, rel_att, rel_msg, 1);
    prep_b_kernel<<<(NTYPES * 3 * 4096 + 255) / 256, 256, 0, s2>>>(pwcat, 384, 128 * 384, 10);
    prep_b_kernel<<<(NTYPES * 4096 + 255) / 256, 256, 0, s2>>>(
        a_w + (size_t)NTYPES * 128 * 128, 128, 128 * 128, 16);
    cudaEventRecord(evB, s2);

    // main: init + count (input-proj epilogue needs only g_last)
    init_kernel<<<(NETYPES * NN + 255) / 256, 256>>>();
    edge_count_kernel<<<(NETYPES * NEDGE + 255) / 256, 256>>>(ei);
    cudaEventRecord(evCnt, 0);

    // s3: scan + scatter concurrent with input GEMM
    cudaStreamWaitEvent(s3, evCnt, 0);
    scan_kernel<<<NETYPES, 1024, 0, s3>>>();
    edge_scatter_kernel<<<(NETYPES * NEDGE + 255) / 256, 256, 0, s3>>>(ei);
    cudaEventRecord(evCSR, s3);

    // input projection + relu + edge-weight scaling -> packed H only
    cudaStreamWaitEvent(0, evA, 0);
    gemm_mma<<<dim3(MB, 2, NTYPES), 256, SMEM_GEMM>>>(
        pAh, pAl, lin_b, 128, nullptr, 0, nullptr, nullptr, nullptr,
        128, 1, ew, pHh, pHl, 0, 0);

    cudaStreamWaitEvent(0, evB, 0);
    cudaStreamWaitEvent(0, evCSR, 0);

    for (int l = 0; l < NL; l++) {
        bool last = (l == NL - 1);

        // fused q | k_rel | v_rel projection (both types)
        gemm_mma<<<dim3(MB, 6, NTYPES), 256, SMEM_GEMM>>>(
            pHh, pHl, pbcat + l * NTYPES * 384, 384, pproj, (size_t)NN * 384,
            nullptr, nullptr, nullptr, 384, 0, nullptr, nullptr, nullptr, 2 + l * 8, 0);

        // main: attn e=0 -> packed A for t=1
        attn_pack_kernel<<<MTILES, 512>>>(rel_p + l * NETYPES * NH, 0, pAh, pAl);
        cudaEventRecord(evAt0, 0);

        // s2: out-proj z=1 (overlaps attn e=1)
        cudaStreamWaitEvent(s2, evAt0, 0);
        gemm_mma<<<dim3(MB, 2, 1), 256, SMEM_GEMM, s2>>>(
            pAh, pAl, a_b + (size_t)l * NTYPES * 128, 128,
            last ? out : nullptr, (size_t)NN * 128,
            pHh, pHl, skip + l * NTYPES, 128, 2, nullptr,
            last ? nullptr : pHh, last ? nullptr : pHl, 8 + l * 8, 1);
        cudaEventRecord(evOut1, s2);

        // main: attn e=1 -> packed A for t=0
        attn_pack_kernel<<<MTILES, 512>>>(rel_p + l * NETYPES * NH, 1, pAh, pAl);

        // main: out-proj z=0
        gemm_mma<<<dim3(MB, 2, 1), 256, SMEM_GEMM>>>(
            pAh, pAl, a_b + (size_t)l * NTYPES * 128, 128,
            last ? out : nullptr, (size_t)NN * 128,
            pHh, pHl, skip + l * NTYPES, 128, 2, nullptr,
            last ? nullptr : pHh, last ? nullptr : pHl, 8 + l * 8, 0);

        // join z=1 out-proj before next layer (or before finishing)
        cudaStreamWaitEvent(0, evOut1, 0);
    }
}

// round 15
// speedup vs baseline: 1.0205x; 1.0205x over previous
#include <cuda_runtime.h>
#include <cuda_bf16.h>
#include <math.h>
#include <stdint.h>

#define NTYPES 2
#define NETYPES 2
#define NN 50000
#define FINDIM 128
#define HIDDIM 128
#define NH 4
#define DH 32
#define NL 2
#define NEDGE 400000
#define MTILES 3125   // NN / 16 exactly

__device__ __constant__ int c_esrc[2] = {0, 1};
__device__ __constant__ int c_edst[2] = {1, 0};

// ---- scratch (__device__ globals; no allocation allowed) ----
__device__ float g_proj[(size_t)NTYPES * NN * 384];
__device__ float g_wcat[(size_t)NTYPES * 128 * 384];
__device__ float g_bcat[NL][NTYPES * 384];
// B fragment image slots: lin:0-1 | wcat0:2-7 | aw0:8-9 | wcat1:10-15 | aw1:16-17
__device__ uint8_t g_bsplit[(size_t)18 * 65536];
__device__ uint4 g_pkA_hi[(size_t)NTYPES * MTILES * 8 * 32];   // x / gelu(agg) images
__device__ uint4 g_pkA_lo[(size_t)NTYPES * MTILES * 8 * 32];
__device__ uint4 g_pkH_hi[(size_t)NTYPES * MTILES * 8 * 32];   // h images
__device__ uint4 g_pkH_lo[(size_t)NTYPES * MTILES * 8 * 32];
__device__ int   g_deg[NETYPES * NN];
__device__ int   g_off[NETYPES * (NN + 1)];
__device__ int   g_cur[NETYPES * NN];
__device__ int   g_srcs[(size_t)NETYPES * NEDGE];
__device__ int   g_last[NTYPES * NN];

__device__ __forceinline__ float gelu_exact(float x) {
    return 0.5f * x * (1.0f + erff(x * 0.7071067811865476f));
}

// split x,y into bf16 hi pair (packed b16x2, x in low half) + lo pair
__device__ __forceinline__ uint32_t split2(float x, float y, uint32_t& lo) {
    __nv_bfloat16 hx = __float2bfloat16(x), hy = __float2bfloat16(y);
    float rx = x - __bfloat162float(hx);
    float ry = y - __bfloat162float(hy);
    __nv_bfloat16 lx = __float2bfloat16(rx), ly = __float2bfloat16(ry);
    uint16_t uhx = *(uint16_t*)&hx, uhy = *(uint16_t*)&hy;
    uint16_t ulx = *(uint16_t*)&lx, uly = *(uint16_t*)&ly;
    lo = ((uint32_t)uly << 16) | ulx;
    return ((uint32_t)uhy << 16) | uhx;
}
// reconstruct fp32 pair from hi/lo packed bf16x2
__device__ __forceinline__ float2 unsplit2(uint32_t h, uint32_t l) {
    __nv_bfloat162 hb = *(__nv_bfloat162*)&h;
    __nv_bfloat162 lb = *(__nv_bfloat162*)&l;
    float2 r;
    r.x = __low2float(hb) + __low2float(lb);
    r.y = __high2float(hb) + __high2float(lb);
    return r;
}

#define MMA_BF16(d, a, b0, b1) \
    asm volatile("mma.sync.aligned.m16n8k16.row.col.f32.bf16.bf16.f32 " \
                 "{%0,%1,%2,%3},{%4,%5,%6,%7},{%8,%9},{%0,%1,%2,%3};" \
                 : "+f"((d)[0]), "+f"((d)[1]), "+f"((d)[2]), "+f"((d)[3]) \
                 : "r"((a).x), "r"((a).y), "r"((a).z), "r"((a).w), "r"(b0), "r"(b1))

// ---------------- init ----------------
__global__ void init_kernel() {
    int idx = blockIdx.x * blockDim.x + threadIdx.x;
    if (idx < NETYPES * NN) g_deg[idx] = 0;
    if (idx < NTYPES * NN)  g_last[idx] = -1;
}

// ---------------- CSR build ----------------
__global__ void edge_count_kernel(const int* __restrict__ ei) {
    int idx = blockIdx.x * blockDim.x + threadIdx.x;
    if (idx >= NETYPES * NEDGE) return;
    int e = idx / NEDGE, j = idx % NEDGE;
    const int* base = ei + (size_t)e * 2 * NEDGE;
    int src = base[j];
    int dst = base[NEDGE + j];
    atomicAdd(&g_deg[e * NN + dst], 1);
    atomicMax(&g_last[c_esrc[e] * NN + src], j);
}

__global__ void scan_kernel() {
    int e = blockIdx.x;
    __shared__ int sh[1024];
    int tidx = threadIdx.x;
    const int CH = (NN + 1023) / 1024;
    int base = tidx * CH;
    int s = 0;
    for (int i = 0; i < CH; i++) { int id = base + i; if (id < NN) s += g_deg[e * NN + id]; }
    sh[tidx] = s;
    __syncthreads();
    for (int o = 1; o < 1024; o <<= 1) {
        int v = (tidx >= o) ? sh[tidx - o] : 0;
        __syncthreads();
        sh[tidx] += v;
        __syncthreads();
    }
    int run = sh[tidx] - s;
    for (int i = 0; i < CH; i++) {
        int id = base + i;
        if (id < NN) {
            g_off[e * (NN + 1) + id] = run;
            g_cur[e * NN + id] = run;
            run += g_deg[e * NN + id];
        }
    }
    if (tidx == 1023) g_off[e * (NN + 1) + NN] = sh[1023];
}

__global__ void edge_scatter_kernel(const int* __restrict__ ei) {
    int idx = blockIdx.x * blockDim.x + threadIdx.x;
    if (idx >= NETYPES * NEDGE) return;
    int e = idx / NEDGE, j = idx % NEDGE;
    const int* base = ei + (size_t)e * 2 * NEDGE;
    int src = base[j];
    int dst = base[NEDGE + j];
    int pos = atomicAdd(&g_cur[e * NN + dst], 1);
    g_srcs[(size_t)e * NEDGE + pos] = src;
}

// ---------------- compose Wcat = [q_w | k_w@R_att | v_w@R_msg] ----------------
__global__ void compose_kernel(const float* __restrict__ kw, const float* __restrict__ kb,
                               const float* __restrict__ qw, const float* __restrict__ qb,
                               const float* __restrict__ vw, const float* __restrict__ vb,
                               const float* __restrict__ ratt, const float* __restrict__ rmsg,
                               int l) {
    int idx = blockIdx.x * blockDim.x + threadIdx.x;
    const int total = NTYPES * 384 * 129;
    if (idx >= total) return;
    int t = idx / (384 * 129);
    int r = idx % (384 * 129);
    int j = r / 129;
    int i = r % 129;
    float val;
    if (j < 128) {
        val = (i < 128) ? qw[(((size_t)l * NTYPES + t) * 128 + i) * 128 + j]
                        : qb[((size_t)l * NTYPES + t) * 128 + j];
    } else {
        bool isK = (j < 256);
        int jo = j - (isK ? 128 : 256);
        int hh = jo >> 5, eo = jo & 31;
        int e = 0;
        for (int ee = 0; ee < NETYPES; ee++) if (c_esrc[ee] == t) e = ee;
        const float* rel = (isK ? ratt : rmsg) +
                           ((((size_t)l * NETYPES + e) * NH + hh) * DH) * DH + eo;
        float s = 0.f;
        if (i < 128) {
            const float* wr = (isK ? kw : vw) + (((size_t)l * NTYPES + t) * 128 + i) * 128 + hh * 32;
            #pragma unroll
            for (int d = 0; d < 32; d++) s += wr[d] * rel[d * 32];
        } else {
            const float* br = (isK ? kb : vb) + ((size_t)l * NTYPES + t) * 128 + hh * 32;
            #pragma unroll
            for (int d = 0; d < 32; d++) s += br[d] * rel[d * 32];
        }
        val = s;
    }
    if (i < 128) g_wcat[((size_t)t * 128 + i) * 384 + j] = val;
    else         g_bcat[l][t * 384 + j] = val;
}

// ---------------- A split+pack: fp32 [z][NN][128] -> mma A-fragment images ----------------
__global__ void split_pack_kernel(const float* __restrict__ src,
                                  uint4* __restrict__ dhi, uint4* __restrict__ dlo) {
    int idx = blockIdx.x * blockDim.x + threadIdx.x;
    const int total = NTYPES * MTILES * 8 * 32;
    if (idx >= total) return;
    int lane = idx & 31;
    int s = (idx >> 5) & 7;
    int mt = (idx >> 8) % MTILES;
    int z = idx / (MTILES * 8 * 32);
    int g = lane >> 2, tig = lane & 3;
    int r0 = mt * 16 + g;
    int c0 = s * 16 + tig * 2;
    const float* S = src + (size_t)z * NN * 128;
    float2 p00 = *(const float2*)(S + (size_t)r0 * 128 + c0);
    float2 p10 = *(const float2*)(S + (size_t)(r0 + 8) * 128 + c0);
    float2 p01 = *(const float2*)(S + (size_t)r0 * 128 + c0 + 8);
    float2 p11 = *(const float2*)(S + (size_t)(r0 + 8) * 128 + c0 + 8);
    uint4 hi, lo;
    hi.x = split2(p00.x, p00.y, lo.x);
    hi.y = split2(p10.x, p10.y, lo.y);
    hi.z = split2(p01.x, p01.y, lo.z);
    hi.w = split2(p11.x, p11.y, lo.w);
    size_t o = (((size_t)z * MTILES + mt) * 8 + s) * 32 + lane;
    dhi[o] = hi;
    dlo[o] = lo;
}

// ---------------- B prep: fp32 W[k][n] -> mma B-fragment images ----------------
__global__ void prep_b_kernel(const float* __restrict__ Wsrc, int Nout, int zstride, int imgBase) {
    int idx = blockIdx.x * blockDim.x + threadIdx.x;
    const int ntl = Nout >> 7;
    const int total = NTYPES * ntl * 8 * 16 * 32;
    if (idx >= total) return;
    int lane = idx & 31;
    int f = (idx >> 5) & 15;
    int s = (idx >> 9) & 7;
    int nt = (idx >> 12) % ntl;
    int z = idx / (ntl * 8 * 16 * 32);
    int g = lane >> 2, tig = lane & 3;
    int n = nt * 128 + f * 8 + g;
    int k0 = s * 16 + tig * 2;
    const float* W = Wsrc + (size_t)z * zstride;
    float w00 = W[(size_t)k0 * Nout + n];
    float w01 = W[(size_t)(k0 + 1) * Nout + n];
    float w10 = W[(size_t)(k0 + 8) * Nout + n];
    float w11 = W[(size_t)(k0 + 9) * Nout + n];
    uint4 q;
    q.x = split2(w00, w01, q.z);
    q.y = split2(w10, w11, q.w);
    uint4* img = (uint4*)(g_bsplit + ((size_t)(imgBase + z * ntl + nt)) * 65536);
    img[(s * 16 + f) * 32 + lane] = q;
}

// ---------------- bf16 3-term mma GEMM (N=128/CTA, R13 config) ----------------
// epi: 0 none, 1 relu + edge-weight row scaling, 2 skip-gated residual (resid from packed images).
// C may be nullptr (pack-only output). z = zoff + blockIdx.z (global type index).
__global__ void __launch_bounds__(256, 2)
gemm_mma(const uint4* __restrict__ Ahi, const uint4* __restrict__ Alo,
         const float* __restrict__ bias, int sB,
         float* C, size_t sC,
         const uint4* resHi, const uint4* resLo,
         const float* __restrict__ skipv,
         int Ntot, int epi, const float* __restrict__ ew,
         uint4* packHi, uint4* packLo, int imgBase, int zoff) {
    extern __shared__ uint4 Bs[];  // 4096 x 16B = 64KB
    const int z = zoff + blockIdx.z, nt = blockIdx.y;
    const int tid = threadIdx.x, warp = tid >> 5, lane = tid & 31;
    const int wm = warp >> 1, wn = warp & 1;
    const int g = lane >> 2, tig = lane & 3;
    const int ntl = gridDim.y;

    {
        const uint4* Bimg = (const uint4*)(g_bsplit + ((size_t)(imgBase + z * ntl + nt)) * 65536);
        #pragma unroll
        for (int i = 0; i < 16; i++) Bs[tid + i * 256] = Bimg[tid + i * 256];
    }
    __syncthreads();

    const int mt0 = blockIdx.x * 8 + wm * 2;
    float acc[2][8][4];
    #pragma unroll
    for (int a = 0; a < 2; a++)
        #pragma unroll
        for (int b = 0; b < 8; b++)
            #pragma unroll
            for (int c = 0; c < 4; c++) acc[a][b][c] = 0.f;

    uint4 aH[2], aL[2], nHbuf[2], nLbuf[2];
    const uint4 zero4 = make_uint4(0, 0, 0, 0);
    #pragma unroll
    for (int mt = 0; mt < 2; mt++) {
        int mtg = mt0 + mt;
        if (mtg < MTILES) {
            size_t o = (((size_t)z * MTILES + mtg) * 8 + 0) * 32 + lane;
            aH[mt] = Ahi[o]; aL[mt] = Alo[o];
        } else { aH[mt] = zero4; aL[mt] = zero4; }
    }

    for (int s = 0; s < 8; s++) {
        if (s < 7) {
            #pragma unroll
            for (int mt = 0; mt < 2; mt++) {
                int mtg = mt0 + mt;
                if (mtg < MTILES) {
                    size_t o = (((size_t)z * MTILES + mtg) * 8 + (s + 1)) * 32 + lane;
                    nHbuf[mt] = Ahi[o]; nLbuf[mt] = Alo[o];
                } else { nHbuf[mt] = zero4; nLbuf[mt] = zero4; }
            }
        }
        #pragma unroll
        for (int f = 0; f < 8; f++) {
            uint4 q = Bs[(s * 16 + wn * 8 + f) * 32 + lane];
            #pragma unroll
            for (int mt = 0; mt < 2; mt++) {
                MMA_BF16(acc[mt][f], aH[mt], q.x, q.y);   // ah*bh
                MMA_BF16(acc[mt][f], aH[mt], q.z, q.w);   // ah*bl
                MMA_BF16(acc[mt][f], aL[mt], q.x, q.y);   // al*bh
            }
        }
        #pragma unroll
        for (int mt = 0; mt < 2; mt++) { aH[mt] = nHbuf[mt]; aL[mt] = nLbuf[mt]; }
    }

    // ---- epilogue ----
    const float* biasz = bias + (size_t)z * sB;
    float* Cz = C ? C + (size_t)z * sC : nullptr;
    float beta = 1.f, omb = 0.f;
    if (epi == 2) {
        float sv = skipv[z];
        beta = 1.f / (1.f + expf(-sv));
        omb = 1.f - beta;
    }
    const int n0 = nt * 128 + wn * 64;
    #pragma unroll
    for (int mt = 0; mt < 2; mt++) {
        int mtg = mt0 + mt;
        if (mtg >= MTILES) continue;
        int r0 = mtg * 16 + g;
        float w0 = 1.f, w1 = 1.f;
        if (epi == 1) {
            int li0 = g_last[z * NN + r0];
            int li1 = g_last[z * NN + r0 + 8];
            if (li0 >= 0) w0 = 1.f / (1.f + expf(-ew[(size_t)z * NEDGE + li0]));
            if (li1 >= 0) w1 = 1.f / (1.f + expf(-ew[(size_t)z * NEDGE + li1]));
        }
        #pragma unroll
        for (int sl = 0; sl < 4; sl++) {
            int fe = sl * 2, fo = fe + 1;
            size_t o = (((size_t)z * MTILES + mtg) * 8 + (wn * 4 + sl)) * 32 + lane;
            float ve[4], vo[4];
            {
                int c = n0 + fe * 8 + tig * 2;
                float2 b2 = *(const float2*)(biasz + c);
                ve[0] = acc[mt][fe][0] + b2.x; ve[1] = acc[mt][fe][1] + b2.y;
                ve[2] = acc[mt][fe][2] + b2.x; ve[3] = acc[mt][fe][3] + b2.y;
            }
            {
                int c = n0 + fo * 8 + tig * 2;
                float2 b2 = *(const float2*)(biasz + c);
                vo[0] = acc[mt][fo][0] + b2.x; vo[1] = acc[mt][fo][1] + b2.y;
                vo[2] = acc[mt][fo][2] + b2.x; vo[3] = acc[mt][fo][3] + b2.y;
            }
            if (epi == 1) {
                #pragma unroll
                for (int i = 0; i < 4; i++) { ve[i] = fmaxf(ve[i], 0.f); vo[i] = fmaxf(vo[i], 0.f); }
                ve[0] *= w0; ve[1] *= w0; ve[2] *= w1; ve[3] *= w1;
                vo[0] *= w0; vo[1] *= w0; vo[2] *= w1; vo[3] *= w1;
            } else if (epi == 2) {
                uint4 rh = resHi[o], rl = resLo[o];
                float2 p0 = unsplit2(rh.x, rl.x);
                float2 p1 = unsplit2(rh.y, rl.y);
                float2 p2 = unsplit2(rh.z, rl.z);
                float2 p3 = unsplit2(rh.w, rl.w);
                ve[0] = beta * ve[0] + omb * p0.x; ve[1] = beta * ve[1] + omb * p0.y;
                ve[2] = beta * ve[2] + omb * p1.x; ve[3] = beta * ve[3] + omb * p1.y;
                vo[0] = beta * vo[0] + omb * p2.x; vo[1] = beta * vo[1] + omb * p2.y;
                vo[2] = beta * vo[2] + omb * p3.x; vo[3] = beta * vo[3] + omb * p3.y;
            }
            if (Cz) {
                int ce = n0 + fe * 8 + tig * 2, co = n0 + fo * 8 + tig * 2;
                *(float2*)(Cz + (size_t)r0 * Ntot + ce)       = make_float2(ve[0], ve[1]);
                *(float2*)(Cz + (size_t)(r0 + 8) * Ntot + ce) = make_float2(ve[2], ve[3]);
                *(float2*)(Cz + (size_t)r0 * Ntot + co)       = make_float2(vo[0], vo[1]);
                *(float2*)(Cz + (size_t)(r0 + 8) * Ntot + co) = make_float2(vo[2], vo[3]);
            }
            if (packHi) {
                uint4 hi, lo;
                hi.x = split2(ve[0], ve[1], lo.x);
                hi.y = split2(ve[2], ve[3], lo.y);
                hi.z = split2(vo[0], vo[1], lo.z);
                hi.w = split2(vo[2], vo[3], lo.w);
                packHi[o] = hi;
                packLo[o] = lo;
            }
        }
    }
}

// ---------------- attention + aggregation + gelu + pack, one edge type per launch ----------------
__global__ void __launch_bounds__(512)
attn_pack_kernel(const float* __restrict__ relp, int e,
                 uint4* __restrict__ dhi, uint4* __restrict__ dlo) {
    __shared__ float sO[16][132];
    int tid = threadIdx.x;
    int warp = tid >> 5, lane = tid & 31;
    int mt = blockIdx.x;
    int n = mt * 16 + warp;
    int t = c_edst[e], s = c_esrc[e];
    const float* projT = g_proj + (size_t)t * NN * 384;
    const float* projS = g_proj + (size_t)s * NN * 384;
    const int* offE = g_off + e * (NN + 1);
    const int* srcE = g_srcs + (size_t)e * NEDGE;
    int hg = lane >> 3;
    float ascale = relp[e * NH + hg] * 0.17677669529663689f;
    float4 q4 = *(const float4*)(projT + (size_t)n * 384 + lane * 4);
    int beg = offE[n], end = offE[n + 1];
    float m = -3.0e38f, ssum = 0.f;
    float4 acc = make_float4(0.f, 0.f, 0.f, 0.f);
    int p2 = beg;
    for (; p2 + 2 <= end; p2 += 2) {
        int u0 = srcE[p2], u1 = srcE[p2 + 1];
        const float* rs0 = projS + (size_t)u0 * 384;
        const float* rs1 = projS + (size_t)u1 * 384;
        float4 k0 = *(const float4*)(rs0 + 128 + lane * 4);
        float4 v0 = *(const float4*)(rs0 + 256 + lane * 4);
        float4 k1 = *(const float4*)(rs1 + 128 + lane * 4);
        float4 v1 = *(const float4*)(rs1 + 256 + lane * 4);
        float d0 = q4.x * k0.x + q4.y * k0.y + q4.z * k0.z + q4.w * k0.w;
        float d1 = q4.x * k1.x + q4.y * k1.y + q4.z * k1.z + q4.w * k1.w;
        d0 += __shfl_xor_sync(0xffffffffu, d0, 1);
        d1 += __shfl_xor_sync(0xffffffffu, d1, 1);
        d0 += __shfl_xor_sync(0xffffffffu, d0, 2);
        d1 += __shfl_xor_sync(0xffffffffu, d1, 2);
        d0 += __shfl_xor_sync(0xffffffffu, d0, 4);
        d1 += __shfl_xor_sync(0xffffffffu, d1, 4);
        float a0 = d0 * ascale, a1 = d1 * ascale;
        float nm = fmaxf(m, fmaxf(a0, a1));
        float sc = __expf(m - nm);
        float pe0 = __expf(a0 - nm), pe1 = __expf(a1 - nm);
        ssum = ssum * sc + pe0 + pe1;
        acc.x = acc.x * sc + pe0 * v0.x + pe1 * v1.x;
        acc.y = acc.y * sc + pe0 * v0.y + pe1 * v1.y;
        acc.z = acc.z * sc + pe0 * v0.z + pe1 * v1.z;
        acc.w = acc.w * sc + pe0 * v0.w + pe1 * v1.w;
        m = nm;
    }
    for (; p2 < end; ++p2) {
        int u = srcE[p2];
        const float* rs = projS + (size_t)u * 384;
        float4 k4 = *(const float4*)(rs + 128 + lane * 4);
        float4 v4 = *(const float4*)(rs + 256 + lane * 4);
        float d = q4.x * k4.x + q4.y * k4.y + q4.z * k4.z + q4.w * k4.w;
        d += __shfl_xor_sync(0xffffffffu, d, 1);
        d += __shfl_xor_sync(0xffffffffu, d, 2);
        d += __shfl_xor_sync(0xffffffffu, d, 4);
        float a = d * ascale;
        float nm = fmaxf(m, a);
        float sc = __expf(m - nm), pe = __expf(a - nm);
        ssum = ssum * sc + pe;
        acc.x = acc.x * sc + pe * v4.x;
        acc.y = acc.y * sc + pe * v4.y;
        acc.z = acc.z * sc + pe * v4.z;
        acc.w = acc.w * sc + pe * v4.w;
        m = nm;
    }
    float inv = 1.f / (ssum + 1e-16f);
    int cb = lane * 4;
    sO[warp][cb + 0] = acc.x * inv;
    sO[warp][cb + 1] = acc.y * inv;
    sO[warp][cb + 2] = acc.z * inv;
    sO[warp][cb + 3] = acc.w * inv;
    __syncthreads();

    if (tid < 256) {
        int sstep = tid >> 5, ln = tid & 31;
        int g = ln >> 2, tig = ln & 3;
        int c0 = sstep * 16 + tig * 2;
        float p00x = gelu_exact(sO[g][c0]);
        float p00y = gelu_exact(sO[g][c0 + 1]);
        float p10x = gelu_exact(sO[g + 8][c0]);
        float p10y = gelu_exact(sO[g + 8][c0 + 1]);
        float p01x = gelu_exact(sO[g][c0 + 8]);
        float p01y = gelu_exact(sO[g][c0 + 9]);
        float p11x = gelu_exact(sO[g + 8][c0 + 8]);
        float p11y = gelu_exact(sO[g + 8][c0 + 9]);
        uint4 hi, lo;
        hi.x = split2(p00x, p00y, lo.x);
        hi.y = split2(p10x, p10y, lo.y);
        hi.z = split2(p01x, p01y, lo.z);
        hi.w = split2(p11x, p11y, lo.w);
        size_t o = (((size_t)t * MTILES + mt) * 8 + sstep) * 32 + ln;
        dhi[o] = hi;
        dlo[o] = lo;
    }
}

// ---------------- launch ----------------
extern "C" void kernel_launch(void* const* d_in, const int* in_sizes, int n_in,
                              void* d_out, int out_size) {
    const float* x       = (const float*)d_in[0];
    const int*   ei      = (const int*)  d_in[1];
    const float* ew      = (const float*)d_in[2];
    const float* lin_w   = (const float*)d_in[3];
    const float* lin_b   = (const float*)d_in[4];
    const float* k_w     = (const float*)d_in[5];
    const float* k_b     = (const float*)d_in[6];
    const float* q_w     = (const float*)d_in[7];
    const float* q_b     = (const float*)d_in[8];
    const float* v_w     = (const float*)d_in[9];
    const float* v_b     = (const float*)d_in[10];
    const float* a_w     = (const float*)d_in[11];
    const float* a_b     = (const float*)d_in[12];
    const float* skip    = (const float*)d_in[13];
    const float* rel_att = (const float*)d_in[14];
    const float* rel_msg = (const float*)d_in[15];
    const float* rel_p   = (const float*)d_in[16];
    float* out = (float*)d_out;

    float *pproj, *pwcat, *pbcat;
    uint4 *pAh, *pAl, *pHh, *pHl;
    cudaGetSymbolAddress((void**)&pproj, g_proj);
    cudaGetSymbolAddress((void**)&pwcat, g_wcat);
    cudaGetSymbolAddress((void**)&pbcat, g_bcat);
    cudaGetSymbolAddress((void**)&pAh,   g_pkA_hi);
    cudaGetSymbolAddress((void**)&pAl,   g_pkA_lo);
    cudaGetSymbolAddress((void**)&pHh,   g_pkH_hi);
    cudaGetSymbolAddress((void**)&pHl,   g_pkH_lo);

    static int inited = 0;
    static cudaStream_t s2, s3;
    static cudaEvent_t evFork, evA, evB, evCnt, evCSR, evQKV, evAt0, evAt1, evOut1;
    const int SMEM_GEMM = 65536;
    if (!inited) {
        cudaFuncSetAttribute(gemm_mma, cudaFuncAttributeMaxDynamicSharedMemorySize, SMEM_GEMM);
        cudaStreamCreateWithFlags(&s2, cudaStreamNonBlocking);
        cudaStreamCreateWithFlags(&s3, cudaStreamNonBlocking);
        cudaEventCreateWithFlags(&evFork, cudaEventDisableTiming);
        cudaEventCreateWithFlags(&evA, cudaEventDisableTiming);
        cudaEventCreateWithFlags(&evB, cudaEventDisableTiming);
        cudaEventCreateWithFlags(&evCnt, cudaEventDisableTiming);
        cudaEventCreateWithFlags(&evCSR, cudaEventDisableTiming);
        cudaEventCreateWithFlags(&evQKV, cudaEventDisableTiming);
        cudaEventCreateWithFlags(&evAt0, cudaEventDisableTiming);
        cudaEventCreateWithFlags(&evAt1, cudaEventDisableTiming);
        cudaEventCreateWithFlags(&evOut1, cudaEventDisableTiming);
        inited = 1;
    }

    const int MB = (NN + 127) / 128;  // 391
    const int PACK_T = NTYPES * MTILES * 8 * 32;

    // ---- fork: weight-side prep on s2, CSR on main / s3 ----
    cudaEventRecord(evFork, 0);
    cudaStreamWaitEvent(s2, evFork, 0);

    // s2: independent prep chain
    split_pack_kernel<<<(PACK_T + 255) / 256, 256, 0, s2>>>(x, pAh, pAl);
    prep_b_kernel<<<(NTYPES * 4096 + 255) / 256, 256, 0, s2>>>(lin_w, 128, 128 * 128, 0);
    cudaEventRecord(evA, s2);
    compose_kernel<<<(NTYPES * 384 * 129 + 255) / 256, 256, 0, s2>>>(
        k_w, k_b, q_w, q_b, v_w, v_b, rel_att, rel_msg, 0);
    prep_b_kernel<<<(NTYPES * 3 * 4096 + 255) / 256, 256, 0, s2>>>(pwcat, 384, 128 * 384, 2);
    prep_b_kernel<<<(NTYPES * 4096 + 255) / 256, 256, 0, s2>>>(a_w, 128, 128 * 128, 8);
    compose_kernel<<<(NTYPES * 384 * 129 + 255) / 256, 256, 0, s2>>>(
        k_w, k_b, q_w, q_b, v_w, v_b, rel_att, rel_msg, 1);
    prep_b_kernel<<<(NTYPES * 3 * 4096 + 255) / 256, 256, 0, s2>>>(pwcat, 384, 128 * 384, 10);
    prep_b_kernel<<<(NTYPES * 4096 + 255) / 256, 256, 0, s2>>>(
        a_w + (size_t)NTYPES * 128 * 128, 128, 128 * 128, 16);
    cudaEventRecord(evB, s2);

    // main: init + count (input-proj epilogue needs only g_last)
    init_kernel<<<(NETYPES * NN + 255) / 256, 256>>>();
    edge_count_kernel<<<(NETYPES * NEDGE + 255) / 256, 256>>>(ei);
    cudaEventRecord(evCnt, 0);

    // s3: scan + scatter concurrent with input GEMM
    cudaStreamWaitEvent(s3, evCnt, 0);
    scan_kernel<<<NETYPES, 1024, 0, s3>>>();
    edge_scatter_kernel<<<(NETYPES * NEDGE + 255) / 256, 256, 0, s3>>>(ei);
    cudaEventRecord(evCSR, s3);

    // input projection + relu + edge-weight scaling -> packed H only
    cudaStreamWaitEvent(0, evA, 0);
    gemm_mma<<<dim3(MB, 1, NTYPES), 256, SMEM_GEMM>>>(
        pAh, pAl, lin_b, 128, nullptr, 0, nullptr, nullptr, nullptr,
        128, 1, ew, pHh, pHl, 0, 0);

    cudaStreamWaitEvent(0, evB, 0);
    cudaStreamWaitEvent(0, evCSR, 0);

    for (int l = 0; l < NL; l++) {
        bool last = (l == NL - 1);

        // fused q | k_rel | v_rel projection (both types)
        gemm_mma<<<dim3(MB, 3, NTYPES), 256, SMEM_GEMM>>>(
            pHh, pHl, pbcat + l * NTYPES * 384, 384, pproj, (size_t)NN * 384,
            nullptr, nullptr, nullptr, 384, 0, nullptr, nullptr, nullptr, 2 + l * 8, 0);
        cudaEventRecord(evQKV, 0);

        // main: attn e=0 -> packed A for t=1
        attn_pack_kernel<<<MTILES, 512>>>(rel_p + l * NETYPES * NH, 0, pAh, pAl);
        cudaEventRecord(evAt0, 0);

        // s2: attn e=1 (concurrent with attn e=0) -> packed A for t=0
        cudaStreamWaitEvent(s2, evQKV, 0);
        attn_pack_kernel<<<MTILES, 512, 0, s2>>>(rel_p + l * NETYPES * NH, 1, pAh, pAl);
        cudaEventRecord(evAt1, s2);

        // s2: out-proj z=1 (needs attn e=0's output; in-order after attn e=1 on s2)
        cudaStreamWaitEvent(s2, evAt0, 0);
        gemm_mma<<<dim3(MB, 1, 1), 256, SMEM_GEMM, s2>>>(
            pAh, pAl, a_b + (size_t)l * NTYPES * 128, 128,
            last ? out : nullptr, (size_t)NN * 128,
            pHh, pHl, skip + l * NTYPES, 128, 2, nullptr,
            last ? nullptr : pHh, last ? nullptr : pHl, 8 + l * 8, 1);
        cudaEventRecord(evOut1, s2);

        // main: out-proj z=0 (needs attn e=1's output)
        cudaStreamWaitEvent(0, evAt1, 0);
        gemm_mma<<<dim3(MB, 1, 1), 256, SMEM_GEMM>>>(
            pAh, pAl, a_b + (size_t)l * NTYPES * 128, 128,
            last ? out : nullptr, (size_t)NN * 128,
            pHh, pHl, skip + l * NTYPES, 128, 2, nullptr,
            last ? nullptr : pHh, last ? nullptr : pHl, 8 + l * 8, 0);

        // join z=1 out-proj before next layer (or before finishing)
        cudaStreamWaitEvent(0, evOut1, 0);
    }
}

// round 16
// speedup vs baseline: 1.1059x; 1.0837x over previous
#include <cuda_runtime.h>
#include <cuda_fp16.h>
#include <math.h>
#include <stdint.h>

#define NTYPES 2
#define NETYPES 2
#define NN 50000
#define FINDIM 128
#define HIDDIM 128
#define NH 4
#define DH 32
#define NL 2
#define NEDGE 400000
#define MTILES 3125   // NN / 16 exactly

__device__ __constant__ int c_esrc[2] = {0, 1};
__device__ __constant__ int c_edst[2] = {1, 0};

// ---- scratch (__device__ globals; no allocation allowed) ----
__device__ float g_proj[(size_t)NTYPES * NN * 384];
__device__ float g_wcat[(size_t)NTYPES * 128 * 384];
__device__ float g_bcat[NL][NTYPES * 384];
// B fragment image slots (fp16 hi only, 32KB used of 64KB stride):
// lin:0-1 | wcat0:2-7 | aw0:8-9 | wcat1:10-15 | aw1:16-17
__device__ uint8_t g_bsplit[(size_t)18 * 65536];
__device__ uint4 g_pkA_hi[(size_t)NTYPES * MTILES * 8 * 32];   // x / gelu(agg) images (fp16 hi/lo)
__device__ uint4 g_pkA_lo[(size_t)NTYPES * MTILES * 8 * 32];
__device__ uint4 g_pkH_hi[(size_t)NTYPES * MTILES * 8 * 32];   // h images
__device__ uint4 g_pkH_lo[(size_t)NTYPES * MTILES * 8 * 32];
__device__ int   g_deg[NETYPES * NN];
__device__ int   g_off[NETYPES * (NN + 1)];
__device__ int   g_cur[NETYPES * NN];
__device__ int   g_srcs[(size_t)NETYPES * NEDGE];
__device__ int   g_last[NTYPES * NN];

__device__ __forceinline__ float gelu_exact(float x) {
    return 0.5f * x * (1.0f + erff(x * 0.7071067811865476f));
}

// split x,y into fp16 hi pair (packed, x in low half) + fp16 lo (residual) pair
__device__ __forceinline__ uint32_t split2(float x, float y, uint32_t& lo) {
    __half hx = __float2half(x), hy = __float2half(y);
    float rx = x - __half2float(hx);
    float ry = y - __half2float(hy);
    __half lx = __float2half(rx), ly = __float2half(ry);
    uint16_t uhx = *(uint16_t*)&hx, uhy = *(uint16_t*)&hy;
    uint16_t ulx = *(uint16_t*)&lx, uly = *(uint16_t*)&ly;
    lo = ((uint32_t)uly << 16) | ulx;
    return ((uint32_t)uhy << 16) | uhx;
}
// reconstruct fp32 pair from hi/lo packed fp16x2
__device__ __forceinline__ float2 unsplit2(uint32_t h, uint32_t l) {
    __half2 hb = *(__half2*)&h;
    __half2 lb = *(__half2*)&l;
    float2 r;
    r.x = __low2float(hb) + __low2float(lb);
    r.y = __high2float(hb) + __high2float(lb);
    return r;
}

#define MMA_F16(d, a, b0, b1) \
    asm volatile("mma.sync.aligned.m16n8k16.row.col.f32.f16.f16.f32 " \
                 "{%0,%1,%2,%3},{%4,%5,%6,%7},{%8,%9},{%0,%1,%2,%3};" \
                 : "+f"((d)[0]), "+f"((d)[1]), "+f"((d)[2]), "+f"((d)[3]) \
                 : "r"((a).x), "r"((a).y), "r"((a).z), "r"((a).w), "r"(b0), "r"(b1))

// ---------------- init ----------------
__global__ void init_kernel() {
    int idx = blockIdx.x * blockDim.x + threadIdx.x;
    if (idx < NETYPES * NN) g_deg[idx] = 0;
    if (idx < NTYPES * NN)  g_last[idx] = -1;
}

// ---------------- CSR build ----------------
__global__ void edge_count_kernel(const int* __restrict__ ei) {
    int idx = blockIdx.x * blockDim.x + threadIdx.x;
    if (idx >= NETYPES * NEDGE) return;
    int e = idx / NEDGE, j = idx % NEDGE;
    const int* base = ei + (size_t)e * 2 * NEDGE;
    int src = base[j];
    int dst = base[NEDGE + j];
    atomicAdd(&g_deg[e * NN + dst], 1);
    atomicMax(&g_last[c_esrc[e] * NN + src], j);
}

__global__ void scan_kernel() {
    int e = blockIdx.x;
    __shared__ int sh[1024];
    int tidx = threadIdx.x;
    const int CH = (NN + 1023) / 1024;
    int base = tidx * CH;
    int s = 0;
    for (int i = 0; i < CH; i++) { int id = base + i; if (id < NN) s += g_deg[e * NN + id]; }
    sh[tidx] = s;
    __syncthreads();
    for (int o = 1; o < 1024; o <<= 1) {
        int v = (tidx >= o) ? sh[tidx - o] : 0;
        __syncthreads();
        sh[tidx] += v;
        __syncthreads();
    }
    int run = sh[tidx] - s;
    for (int i = 0; i < CH; i++) {
        int id = base + i;
        if (id < NN) {
            g_off[e * (NN + 1) + id] = run;
            g_cur[e * NN + id] = run;
            run += g_deg[e * NN + id];
        }
    }
    if (tidx == 1023) g_off[e * (NN + 1) + NN] = sh[1023];
}

__global__ void edge_scatter_kernel(const int* __restrict__ ei) {
    int idx = blockIdx.x * blockDim.x + threadIdx.x;
    if (idx >= NETYPES * NEDGE) return;
    int e = idx / NEDGE, j = idx % NEDGE;
    const int* base = ei + (size_t)e * 2 * NEDGE;
    int src = base[j];
    int dst = base[NEDGE + j];
    int pos = atomicAdd(&g_cur[e * NN + dst], 1);
    g_srcs[(size_t)e * NEDGE + pos] = src;
}

// ---------------- compose Wcat = [q_w | k_w@R_att | v_w@R_msg] ----------------
__global__ void compose_kernel(const float* __restrict__ kw, const float* __restrict__ kb,
                               const float* __restrict__ qw, const float* __restrict__ qb,
                               const float* __restrict__ vw, const float* __restrict__ vb,
                               const float* __restrict__ ratt, const float* __restrict__ rmsg,
                               int l) {
    int idx = blockIdx.x * blockDim.x + threadIdx.x;
    const int total = NTYPES * 384 * 129;
    if (idx >= total) return;
    int t = idx / (384 * 129);
    int r = idx % (384 * 129);
    int j = r / 129;
    int i = r % 129;
    float val;
    if (j < 128) {
        val = (i < 128) ? qw[(((size_t)l * NTYPES + t) * 128 + i) * 128 + j]
                        : qb[((size_t)l * NTYPES + t) * 128 + j];
    } else {
        bool isK = (j < 256);
        int jo = j - (isK ? 128 : 256);
        int hh = jo >> 5, eo = jo & 31;
        int e = 0;
        for (int ee = 0; ee < NETYPES; ee++) if (c_esrc[ee] == t) e = ee;
        const float* rel = (isK ? ratt : rmsg) +
                           ((((size_t)l * NETYPES + e) * NH + hh) * DH) * DH + eo;
        float s = 0.f;
        if (i < 128) {
            const float* wr = (isK ? kw : vw) + (((size_t)l * NTYPES + t) * 128 + i) * 128 + hh * 32;
            #pragma unroll
            for (int d = 0; d < 32; d++) s += wr[d] * rel[d * 32];
        } else {
            const float* br = (isK ? kb : vb) + ((size_t)l * NTYPES + t) * 128 + hh * 32;
            #pragma unroll
            for (int d = 0; d < 32; d++) s += br[d] * rel[d * 32];
        }
        val = s;
    }
    if (i < 128) g_wcat[((size_t)t * 128 + i) * 384 + j] = val;
    else         g_bcat[l][t * 384 + j] = val;
}

// ---------------- A split+pack: fp32 [z][NN][128] -> mma A-fragment images ----------------
__global__ void split_pack_kernel(const float* __restrict__ src,
                                  uint4* __restrict__ dhi, uint4* __restrict__ dlo) {
    int idx = blockIdx.x * blockDim.x + threadIdx.x;
    const int total = NTYPES * MTILES * 8 * 32;
    if (idx >= total) return;
    int lane = idx & 31;
    int s = (idx >> 5) & 7;
    int mt = (idx >> 8) % MTILES;
    int z = idx / (MTILES * 8 * 32);
    int g = lane >> 2, tig = lane & 3;
    int r0 = mt * 16 + g;
    int c0 = s * 16 + tig * 2;
    const float* S = src + (size_t)z * NN * 128;
    float2 p00 = *(const float2*)(S + (size_t)r0 * 128 + c0);
    float2 p10 = *(const float2*)(S + (size_t)(r0 + 8) * 128 + c0);
    float2 p01 = *(const float2*)(S + (size_t)r0 * 128 + c0 + 8);
    float2 p11 = *(const float2*)(S + (size_t)(r0 + 8) * 128 + c0 + 8);
    uint4 hi, lo;
    hi.x = split2(p00.x, p00.y, lo.x);
    hi.y = split2(p10.x, p10.y, lo.y);
    hi.z = split2(p01.x, p01.y, lo.z);
    hi.w = split2(p11.x, p11.y, lo.w);
    size_t o = (((size_t)z * MTILES + mt) * 8 + s) * 32 + lane;
    dhi[o] = hi;
    dlo[o] = lo;
}

// ---------------- B prep: fp32 W[k][n] -> fp16 B-fragment images (hi only) ----------------
__global__ void prep_b_kernel(const float* __restrict__ Wsrc, int Nout, int zstride, int imgBase) {
    int idx = blockIdx.x * blockDim.x + threadIdx.x;
    const int ntl = Nout >> 7;
    const int total = NTYPES * ntl * 8 * 16 * 32;
    if (idx >= total) return;
    int lane = idx & 31;
    int f = (idx >> 5) & 15;
    int s = (idx >> 9) & 7;
    int nt = (idx >> 12) % ntl;
    int z = idx / (ntl * 8 * 16 * 32);
    int g = lane >> 2, tig = lane & 3;
    int n = nt * 128 + f * 8 + g;
    int k0 = s * 16 + tig * 2;
    const float* W = Wsrc + (size_t)z * zstride;
    float w00 = W[(size_t)k0 * Nout + n];
    float w01 = W[(size_t)(k0 + 1) * Nout + n];
    float w10 = W[(size_t)(k0 + 8) * Nout + n];
    float w11 = W[(size_t)(k0 + 9) * Nout + n];
    uint32_t l0, l1;
    uint32_t h0 = split2(w00, w01, l0);
    uint32_t h1 = split2(w10, w11, l1);
    uint2* img = (uint2*)(g_bsplit + ((size_t)(imgBase + z * ntl + nt)) * 65536);
    img[(s * 16 + f) * 32 + lane] = make_uint2(h0, h1);
}

// ---------------- fp16 2-term mma GEMM: exact-A x fp16(B) ----------------
// a*b = (ah+al)*bh with fp16 split => B rounded to fp16, A exact.
// epi: 0 none, 1 relu + edge-weight row scaling, 2 skip-gated residual (resid from packed images).
// C may be nullptr (pack-only output). z = zoff + blockIdx.z.
__global__ void __launch_bounds__(256, 2)
gemm_mma(const uint4* __restrict__ Ahi, const uint4* __restrict__ Alo,
         const float* __restrict__ bias, int sB,
         float* C, size_t sC,
         const uint4* resHi, const uint4* resLo,
         const float* __restrict__ skipv,
         int Ntot, int epi, const float* __restrict__ ew,
         uint4* packHi, uint4* packLo, int imgBase, int zoff) {
    extern __shared__ uint2 Bs[];  // 4096 x 8B = 32KB
    const int z = zoff + blockIdx.z, nt = blockIdx.y;
    const int tid = threadIdx.x, warp = tid >> 5, lane = tid & 31;
    const int wm = warp >> 1, wn = warp & 1;
    const int g = lane >> 2, tig = lane & 3;
    const int ntl = gridDim.y;

    {
        const uint4* Bimg = (const uint4*)(g_bsplit + ((size_t)(imgBase + z * ntl + nt)) * 65536);
        uint4* Bs4 = (uint4*)Bs;
        #pragma unroll
        for (int i = 0; i < 8; i++) Bs4[tid + i * 256] = Bimg[tid + i * 256];
    }
    __syncthreads();

    const int mt0 = blockIdx.x * 8 + wm * 2;
    float acc[2][8][4];
    #pragma unroll
    for (int a = 0; a < 2; a++)
        #pragma unroll
        for (int b = 0; b < 8; b++)
            #pragma unroll
            for (int c = 0; c < 4; c++) acc[a][b][c] = 0.f;

    uint4 aH[2], aL[2], nHbuf[2], nLbuf[2];
    const uint4 zero4 = make_uint4(0, 0, 0, 0);
    #pragma unroll
    for (int mt = 0; mt < 2; mt++) {
        int mtg = mt0 + mt;
        if (mtg < MTILES) {
            size_t o = (((size_t)z * MTILES + mtg) * 8 + 0) * 32 + lane;
            aH[mt] = Ahi[o]; aL[mt] = Alo[o];
        } else { aH[mt] = zero4; aL[mt] = zero4; }
    }

    for (int s = 0; s < 8; s++) {
        if (s < 7) {
            #pragma unroll
            for (int mt = 0; mt < 2; mt++) {
                int mtg = mt0 + mt;
                if (mtg < MTILES) {
                    size_t o = (((size_t)z * MTILES + mtg) * 8 + (s + 1)) * 32 + lane;
                    nHbuf[mt] = Ahi[o]; nLbuf[mt] = Alo[o];
                } else { nHbuf[mt] = zero4; nLbuf[mt] = zero4; }
            }
        }
        #pragma unroll
        for (int f = 0; f < 8; f++) {
            uint2 q = Bs[(s * 16 + wn * 8 + f) * 32 + lane];
            #pragma unroll
            for (int mt = 0; mt < 2; mt++) {
                MMA_F16(acc[mt][f], aH[mt], q.x, q.y);   // ah*bh
                MMA_F16(acc[mt][f], aL[mt], q.x, q.y);   // al*bh
            }
        }
        #pragma unroll
        for (int mt = 0; mt < 2; mt++) { aH[mt] = nHbuf[mt]; aL[mt] = nLbuf[mt]; }
    }

    // ---- epilogue ----
    const float* biasz = bias + (size_t)z * sB;
    float* Cz = C ? C + (size_t)z * sC : nullptr;
    float beta = 1.f, omb = 0.f;
    if (epi == 2) {
        float sv = skipv[z];
        beta = 1.f / (1.f + expf(-sv));
        omb = 1.f - beta;
    }
    const int n0 = nt * 128 + wn * 64;
    #pragma unroll
    for (int mt = 0; mt < 2; mt++) {
        int mtg = mt0 + mt;
        if (mtg >= MTILES) continue;
        int r0 = mtg * 16 + g;
        float w0 = 1.f, w1 = 1.f;
        if (epi == 1) {
            int li0 = g_last[z * NN + r0];
            int li1 = g_last[z * NN + r0 + 8];
            if (li0 >= 0) w0 = 1.f / (1.f + expf(-ew[(size_t)z * NEDGE + li0]));
            if (li1 >= 0) w1 = 1.f / (1.f + expf(-ew[(size_t)z * NEDGE + li1]));
        }
        #pragma unroll
        for (int sl = 0; sl < 4; sl++) {
            int fe = sl * 2, fo = fe + 1;
            size_t o = (((size_t)z * MTILES + mtg) * 8 + (wn * 4 + sl)) * 32 + lane;
            float ve[4], vo[4];
            {
                int c = n0 + fe * 8 + tig * 2;
                float2 b2 = *(const float2*)(biasz + c);
                ve[0] = acc[mt][fe][0] + b2.x; ve[1] = acc[mt][fe][1] + b2.y;
                ve[2] = acc[mt][fe][2] + b2.x; ve[3] = acc[mt][fe][3] + b2.y;
            }
            {
                int c = n0 + fo * 8 + tig * 2;
                float2 b2 = *(const float2*)(biasz + c);
                vo[0] = acc[mt][fo][0] + b2.x; vo[1] = acc[mt][fo][1] + b2.y;
                vo[2] = acc[mt][fo][2] + b2.x; vo[3] = acc[mt][fo][3] + b2.y;
            }
            if (epi == 1) {
                #pragma unroll
                for (int i = 0; i < 4; i++) { ve[i] = fmaxf(ve[i], 0.f); vo[i] = fmaxf(vo[i], 0.f); }
                ve[0] *= w0; ve[1] *= w0; ve[2] *= w1; ve[3] *= w1;
                vo[0] *= w0; vo[1] *= w0; vo[2] *= w1; vo[3] *= w1;
            } else if (epi == 2) {
                uint4 rh = resHi[o], rl = resLo[o];
                float2 p0 = unsplit2(rh.x, rl.x);
                float2 p1 = unsplit2(rh.y, rl.y);
                float2 p2 = unsplit2(rh.z, rl.z);
                float2 p3 = unsplit2(rh.w, rl.w);
                ve[0] = beta * ve[0] + omb * p0.x; ve[1] = beta * ve[1] + omb * p0.y;
                ve[2] = beta * ve[2] + omb * p1.x; ve[3] = beta * ve[3] + omb * p1.y;
                vo[0] = beta * vo[0] + omb * p2.x; vo[1] = beta * vo[1] + omb * p2.y;
                vo[2] = beta * vo[2] + omb * p3.x; vo[3] = beta * vo[3] + omb * p3.y;
            }
            if (Cz) {
                int ce = n0 + fe * 8 + tig * 2, co = n0 + fo * 8 + tig * 2;
                *(float2*)(Cz + (size_t)r0 * Ntot + ce)       = make_float2(ve[0], ve[1]);
                *(float2*)(Cz + (size_t)(r0 + 8) * Ntot + ce) = make_float2(ve[2], ve[3]);
                *(float2*)(Cz + (size_t)r0 * Ntot + co)       = make_float2(vo[0], vo[1]);
                *(float2*)(Cz + (size_t)(r0 + 8) * Ntot + co) = make_float2(vo[2], vo[3]);
            }
            if (packHi) {
                uint4 hi, lo;
                hi.x = split2(ve[0], ve[1], lo.x);
                hi.y = split2(ve[2], ve[3], lo.y);
                hi.z = split2(vo[0], vo[1], lo.z);
                hi.w = split2(vo[2], vo[3], lo.w);
                packHi[o] = hi;
                packLo[o] = lo;
            }
        }
    }
}

// ---------------- attention + aggregation + gelu + pack, one edge type per launch ----------------
__global__ void __launch_bounds__(512)
attn_pack_kernel(const float* __restrict__ relp, int e,
                 uint4* __restrict__ dhi, uint4* __restrict__ dlo) {
    __shared__ float sO[16][132];
    int tid = threadIdx.x;
    int warp = tid >> 5, lane = tid & 31;
    int mt = blockIdx.x;
    int n = mt * 16 + warp;
    int t = c_edst[e], s = c_esrc[e];
    const float* projT = g_proj + (size_t)t * NN * 384;
    const float* projS = g_proj + (size_t)s * NN * 384;
    const int* offE = g_off + e * (NN + 1);
    const int* srcE = g_srcs + (size_t)e * NEDGE;
    int hg = lane >> 3;
    float ascale = relp[e * NH + hg] * 0.17677669529663689f;
    float4 q4 = *(const float4*)(projT + (size_t)n * 384 + lane * 4);
    int beg = offE[n], end = offE[n + 1];
    float m = -3.0e38f, ssum = 0.f;
    float4 acc = make_float4(0.f, 0.f, 0.f, 0.f);
    int p2 = beg;
    for (; p2 + 2 <= end; p2 += 2) {
        int u0 = srcE[p2], u1 = srcE[p2 + 1];
        const float* rs0 = projS + (size_t)u0 * 384;
        const float* rs1 = projS + (size_t)u1 * 384;
        float4 k0 = *(const float4*)(rs0 + 128 + lane * 4);
        float4 v0 = *(const float4*)(rs0 + 256 + lane * 4);
        float4 k1 = *(const float4*)(rs1 + 128 + lane * 4);
        float4 v1 = *(const float4*)(rs1 + 256 + lane * 4);
        float d0 = q4.x * k0.x + q4.y * k0.y + q4.z * k0.z + q4.w * k0.w;
        float d1 = q4.x * k1.x + q4.y * k1.y + q4.z * k1.z + q4.w * k1.w;
        d0 += __shfl_xor_sync(0xffffffffu, d0, 1);
        d1 += __shfl_xor_sync(0xffffffffu, d1, 1);
        d0 += __shfl_xor_sync(0xffffffffu, d0, 2);
        d1 += __shfl_xor_sync(0xffffffffu, d1, 2);
        d0 += __shfl_xor_sync(0xffffffffu, d0, 4);
        d1 += __shfl_xor_sync(0xffffffffu, d1, 4);
        float a0 = d0 * ascale, a1 = d1 * ascale;
        float nm = fmaxf(m, fmaxf(a0, a1));
        float sc = __expf(m - nm);
        float pe0 = __expf(a0 - nm), pe1 = __expf(a1 - nm);
        ssum = ssum * sc + pe0 + pe1;
        acc.x = acc.x * sc + pe0 * v0.x + pe1 * v1.x;
        acc.y = acc.y * sc + pe0 * v0.y + pe1 * v1.y;
        acc.z = acc.z * sc + pe0 * v0.z + pe1 * v1.z;
        acc.w = acc.w * sc + pe0 * v0.w + pe1 * v1.w;
        m = nm;
    }
    for (; p2 < end; ++p2) {
        int u = srcE[p2];
        const float* rs = projS + (size_t)u * 384;
        float4 k4 = *(const float4*)(rs + 128 + lane * 4);
        float4 v4 = *(const float4*)(rs + 256 + lane * 4);
        float d = q4.x * k4.x + q4.y * k4.y + q4.z * k4.z + q4.w * k4.w;
        d += __shfl_xor_sync(0xffffffffu, d, 1);
        d += __shfl_xor_sync(0xffffffffu, d, 2);
        d += __shfl_xor_sync(0xffffffffu, d, 4);
        float a = d * ascale;
        float nm = fmaxf(m, a);
        float sc = __expf(m - nm), pe = __expf(a - nm);
        ssum = ssum * sc + pe;
        acc.x = acc.x * sc + pe * v4.x;
        acc.y = acc.y * sc + pe * v4.y;
        acc.z = acc.z * sc + pe * v4.z;
        acc.w = acc.w * sc + pe * v4.w;
        m = nm;
    }
    float inv = 1.f / (ssum + 1e-16f);
    int cb = lane * 4;
    sO[warp][cb + 0] = acc.x * inv;
    sO[warp][cb + 1] = acc.y * inv;
    sO[warp][cb + 2] = acc.z * inv;
    sO[warp][cb + 3] = acc.w * inv;
    __syncthreads();

    if (tid < 256) {
        int sstep = tid >> 5, ln = tid & 31;
        int g = ln >> 2, tig = ln & 3;
        int c0 = sstep * 16 + tig * 2;
        float p00x = gelu_exact(sO[g][c0]);
        float p00y = gelu_exact(sO[g][c0 + 1]);
        float p10x = gelu_exact(sO[g + 8][c0]);
        float p10y = gelu_exact(sO[g + 8][c0 + 1]);
        float p01x = gelu_exact(sO[g][c0 + 8]);
        float p01y = gelu_exact(sO[g][c0 + 9]);
        float p11x = gelu_exact(sO[g + 8][c0 + 8]);
        float p11y = gelu_exact(sO[g + 8][c0 + 9]);
        uint4 hi, lo;
        hi.x = split2(p00x, p00y, lo.x);
        hi.y = split2(p10x, p10y, lo.y);
        hi.z = split2(p01x, p01y, lo.z);
        hi.w = split2(p11x, p11y, lo.w);
        size_t o = (((size_t)t * MTILES + mt) * 8 + sstep) * 32 + ln;
        dhi[o] = hi;
        dlo[o] = lo;
    }
}

// ---------------- launch ----------------
extern "C" void kernel_launch(void* const* d_in, const int* in_sizes, int n_in,
                              void* d_out, int out_size) {
    const float* x       = (const float*)d_in[0];
    const int*   ei      = (const int*)  d_in[1];
    const float* ew      = (const float*)d_in[2];
    const float* lin_w   = (const float*)d_in[3];
    const float* lin_b   = (const float*)d_in[4];
    const float* k_w     = (const float*)d_in[5];
    const float* k_b     = (const float*)d_in[6];
    const float* q_w     = (const float*)d_in[7];
    const float* q_b     = (const float*)d_in[8];
    const float* v_w     = (const float*)d_in[9];
    const float* v_b     = (const float*)d_in[10];
    const float* a_w     = (const float*)d_in[11];
    const float* a_b     = (const float*)d_in[12];
    const float* skip    = (const float*)d_in[13];
    const float* rel_att = (const float*)d_in[14];
    const float* rel_msg = (const float*)d_in[15];
    const float* rel_p   = (const float*)d_in[16];
    float* out = (float*)d_out;

    float *pproj, *pwcat, *pbcat;
    uint4 *pAh, *pAl, *pHh, *pHl;
    cudaGetSymbolAddress((void**)&pproj, g_proj);
    cudaGetSymbolAddress((void**)&pwcat, g_wcat);
    cudaGetSymbolAddress((void**)&pbcat, g_bcat);
    cudaGetSymbolAddress((void**)&pAh,   g_pkA_hi);
    cudaGetSymbolAddress((void**)&pAl,   g_pkA_lo);
    cudaGetSymbolAddress((void**)&pHh,   g_pkH_hi);
    cudaGetSymbolAddress((void**)&pHl,   g_pkH_lo);

    static int inited = 0;
    static cudaStream_t s2, s3;
    static cudaEvent_t evFork, evA, evB, evCnt, evCSR, evQKV, evAt0, evAt1, evOut1;
    const int SMEM_GEMM = 32768;
    if (!inited) {
        cudaFuncSetAttribute(gemm_mma, cudaFuncAttributeMaxDynamicSharedMemorySize, SMEM_GEMM);
        cudaStreamCreateWithFlags(&s2, cudaStreamNonBlocking);
        cudaStreamCreateWithFlags(&s3, cudaStreamNonBlocking);
        cudaEventCreateWithFlags(&evFork, cudaEventDisableTiming);
        cudaEventCreateWithFlags(&evA, cudaEventDisableTiming);
        cudaEventCreateWithFlags(&evB, cudaEventDisableTiming);
        cudaEventCreateWithFlags(&evCnt, cudaEventDisableTiming);
        cudaEventCreateWithFlags(&evCSR, cudaEventDisableTiming);
        cudaEventCreateWithFlags(&evQKV, cudaEventDisableTiming);
        cudaEventCreateWithFlags(&evAt0, cudaEventDisableTiming);
        cudaEventCreateWithFlags(&evAt1, cudaEventDisableTiming);
        cudaEventCreateWithFlags(&evOut1, cudaEventDisableTiming);
        inited = 1;
    }

    const int MB = (NN + 127) / 128;  // 391
    const int PACK_T = NTYPES * MTILES * 8 * 32;

    // ---- fork: weight-side prep on s2, CSR on main / s3 ----
    cudaEventRecord(evFork, 0);
    cudaStreamWaitEvent(s2, evFork, 0);

    // s2: independent prep chain
    split_pack_kernel<<<(PACK_T + 255) / 256, 256, 0, s2>>>(x, pAh, pAl);
    prep_b_kernel<<<(NTYPES * 4096 + 255) / 256, 256, 0, s2>>>(lin_w, 128, 128 * 128, 0);
    cudaEventRecord(evA, s2);
    compose_kernel<<<(NTYPES * 384 * 129 + 255) / 256, 256, 0, s2>>>(
        k_w, k_b, q_w, q_b, v_w, v_b, rel_att, rel_msg, 0);
    prep_b_kernel<<<(NTYPES * 3 * 4096 + 255) / 256, 256, 0, s2>>>(pwcat, 384, 128 * 384, 2);
    prep_b_kernel<<<(NTYPES * 4096 + 255) / 256, 256, 0, s2>>>(a_w, 128, 128 * 128, 8);
    compose_kernel<<<(NTYPES * 384 * 129 + 255) / 256, 256, 0, s2>>>(
        k_w, k_b, q_w, q_b, v_w, v_b, rel_att, rel_msg, 1);
    prep_b_kernel<<<(NTYPES * 3 * 4096 + 255) / 256, 256, 0, s2>>>(pwcat, 384, 128 * 384, 10);
    prep_b_kernel<<<(NTYPES * 4096 + 255) / 256, 256, 0, s2>>>(
        a_w + (size_t)NTYPES * 128 * 128, 128, 128 * 128, 16);
    cudaEventRecord(evB, s2);

    // main: init + count (input-proj epilogue needs only g_last)
    init_kernel<<<(NETYPES * NN + 255) / 256, 256>>>();
    edge_count_kernel<<<(NETYPES * NEDGE + 255) / 256, 256>>>(ei);
    cudaEventRecord(evCnt, 0);

    // s3: scan + scatter concurrent with input GEMM
    cudaStreamWaitEvent(s3, evCnt, 0);
    scan_kernel<<<NETYPES, 1024, 0, s3>>>();
    edge_scatter_kernel<<<(NETYPES * NEDGE + 255) / 256, 256, 0, s3>>>(ei);
    cudaEventRecord(evCSR, s3);

    // input projection + relu + edge-weight scaling -> packed H only
    cudaStreamWaitEvent(0, evA, 0);
    gemm_mma<<<dim3(MB, 1, NTYPES), 256, SMEM_GEMM>>>(
        pAh, pAl, lin_b, 128, nullptr, 0, nullptr, nullptr, nullptr,
        128, 1, ew, pHh, pHl, 0, 0);

    cudaStreamWaitEvent(0, evB, 0);
    cudaStreamWaitEvent(0, evCSR, 0);

    for (int l = 0; l < NL; l++) {
        bool last = (l == NL - 1);

        // fused q | k_rel | v_rel projection (both types)
        gemm_mma<<<dim3(MB, 3, NTYPES), 256, SMEM_GEMM>>>(
            pHh, pHl, pbcat + l * NTYPES * 384, 384, pproj, (size_t)NN * 384,
            nullptr, nullptr, nullptr, 384, 0, nullptr, nullptr, nullptr, 2 + l * 8, 0);
        cudaEventRecord(evQKV, 0);

        // main: attn e=0 -> packed A for t=1
        attn_pack_kernel<<<MTILES, 512>>>(rel_p + l * NETYPES * NH, 0, pAh, pAl);
        cudaEventRecord(evAt0, 0);

        // s2: attn e=1 (concurrent with attn e=0) -> packed A for t=0
        cudaStreamWaitEvent(s2, evQKV, 0);
        attn_pack_kernel<<<MTILES, 512, 0, s2>>>(rel_p + l * NETYPES * NH, 1, pAh, pAl);
        cudaEventRecord(evAt1, s2);

        // s2: out-proj z=1 (needs attn e=0's output; in-order after attn e=1 on s2)
        cudaStreamWaitEvent(s2, evAt0, 0);
        gemm_mma<<<dim3(MB, 1, 1), 256, SMEM_GEMM, s2>>>(
            pAh, pAl, a_b + (size_t)l * NTYPES * 128, 128,
            last ? out : nullptr, (size_t)NN * 128,
            pHh, pHl, skip + l * NTYPES, 128, 2, nullptr,
            last ? nullptr : pHh, last ? nullptr : pHl, 8 + l * 8, 1);
        cudaEventRecord(evOut1, s2);

        // main: out-proj z=0 (needs attn e=1's output)
        cudaStreamWaitEvent(0, evAt1, 0);
        gemm_mma<<<dim3(MB, 1, 1), 256, SMEM_GEMM>>>(
            pAh, pAl, a_b + (size_t)l * NTYPES * 128, 128,
            last ? out : nullptr, (size_t)NN * 128,
            pHh, pHl, skip + l * NTYPES, 128, 2, nullptr,
            last ? nullptr : pHh, last ? nullptr : pHl, 8 + l * 8, 0);

        // join z=1 out-proj before next layer (or before finishing)
        cudaStreamWaitEvent(0, evOut1, 0);
    }
}

// round 17
// speedup vs baseline: 1.1109x; 1.0045x over previous
#include <cuda_runtime.h>
#include <cuda_fp16.h>
#include <math.h>
#include <stdint.h>

#define NTYPES 2
#define NETYPES 2
#define NN 50000
#define FINDIM 128
#define HIDDIM 128
#define NH 4
#define DH 32
#define NL 2
#define NEDGE 400000
#define MTILES 3125   // NN / 16 exactly

__device__ __constant__ int c_esrc[2] = {0, 1};
__device__ __constant__ int c_edst[2] = {1, 0};

// ---- scratch (__device__ globals; no allocation allowed) ----
// proj row (1024B): [q:128 fp32][k:128 fp16][v:128 fp16]
__device__ float g_proj[(size_t)NTYPES * NN * 256];
__device__ float g_wcat[(size_t)NTYPES * 128 * 384];
__device__ float g_bcat[NL][NTYPES * 384];
// B fragment image slots (fp16 hi only, 32KB used of 64KB stride):
// lin:0-1 | wcat0:2-7 | aw0:8-9 | wcat1:10-15 | aw1:16-17
__device__ uint8_t g_bsplit[(size_t)18 * 65536];
__device__ uint4 g_pkA_hi[(size_t)NTYPES * MTILES * 8 * 32];   // x / gelu(agg) images (fp16 hi/lo)
__device__ uint4 g_pkA_lo[(size_t)NTYPES * MTILES * 8 * 32];
__device__ uint4 g_pkH_hi[(size_t)NTYPES * MTILES * 8 * 32];   // h images
__device__ uint4 g_pkH_lo[(size_t)NTYPES * MTILES * 8 * 32];
__device__ int   g_deg[NETYPES * NN];
__device__ int   g_off[NETYPES * (NN + 1)];
__device__ int   g_cur[NETYPES * NN];
__device__ int   g_srcs[(size_t)NETYPES * NEDGE];
__device__ int   g_last[NTYPES * NN];

__device__ __forceinline__ float gelu_exact(float x) {
    return 0.5f * x * (1.0f + erff(x * 0.7071067811865476f));
}

// split x,y into fp16 hi pair (packed, x in low half) + fp16 lo (residual) pair
__device__ __forceinline__ uint32_t split2(float x, float y, uint32_t& lo) {
    __half hx = __float2half(x), hy = __float2half(y);
    float rx = x - __half2float(hx);
    float ry = y - __half2float(hy);
    __half lx = __float2half(rx), ly = __float2half(ry);
    uint16_t uhx = *(uint16_t*)&hx, uhy = *(uint16_t*)&hy;
    uint16_t ulx = *(uint16_t*)&lx, uly = *(uint16_t*)&ly;
    lo = ((uint32_t)uly << 16) | ulx;
    return ((uint32_t)uhy << 16) | uhx;
}
// reconstruct fp32 pair from hi/lo packed fp16x2
__device__ __forceinline__ float2 unsplit2(uint32_t h, uint32_t l) {
    __half2 hb = *(__half2*)&h;
    __half2 lb = *(__half2*)&l;
    float2 r;
    r.x = __low2float(hb) + __low2float(lb);
    r.y = __high2float(hb) + __high2float(lb);
    return r;
}

#define MMA_F16(d, a, b0, b1) \
    asm volatile("mma.sync.aligned.m16n8k16.row.col.f32.f16.f16.f32 " \
                 "{%0,%1,%2,%3},{%4,%5,%6,%7},{%8,%9},{%0,%1,%2,%3};" \
                 : "+f"((d)[0]), "+f"((d)[1]), "+f"((d)[2]), "+f"((d)[3]) \
                 : "r"((a).x), "r"((a).y), "r"((a).z), "r"((a).w), "r"(b0), "r"(b1))

// ---------------- init ----------------
__global__ void init_kernel() {
    int idx = blockIdx.x * blockDim.x + threadIdx.x;
    if (idx < NETYPES * NN) g_deg[idx] = 0;
    if (idx < NTYPES * NN)  g_last[idx] = -1;
}

// ---------------- CSR build ----------------
__global__ void edge_count_kernel(const int* __restrict__ ei) {
    int idx = blockIdx.x * blockDim.x + threadIdx.x;
    if (idx >= NETYPES * NEDGE) return;
    int e = idx / NEDGE, j = idx % NEDGE;
    const int* base = ei + (size_t)e * 2 * NEDGE;
    int src = base[j];
    int dst = base[NEDGE + j];
    atomicAdd(&g_deg[e * NN + dst], 1);
    atomicMax(&g_last[c_esrc[e] * NN + src], j);
}

__global__ void scan_kernel() {
    int e = blockIdx.x;
    __shared__ int sh[1024];
    int tidx = threadIdx.x;
    const int CH = (NN + 1023) / 1024;
    int base = tidx * CH;
    int s = 0;
    for (int i = 0; i < CH; i++) { int id = base + i; if (id < NN) s += g_deg[e * NN + id]; }
    sh[tidx] = s;
    __syncthreads();
    for (int o = 1; o < 1024; o <<= 1) {
        int v = (tidx >= o) ? sh[tidx - o] : 0;
        __syncthreads();
        sh[tidx] += v;
        __syncthreads();
    }
    int run = sh[tidx] - s;
    for (int i = 0; i < CH; i++) {
        int id = base + i;
        if (id < NN) {
            g_off[e * (NN + 1) + id] = run;
            g_cur[e * NN + id] = run;
            run += g_deg[e * NN + id];
        }
    }
    if (tidx == 1023) g_off[e * (NN + 1) + NN] = sh[1023];
}

__global__ void edge_scatter_kernel(const int* __restrict__ ei) {
    int idx = blockIdx.x * blockDim.x + threadIdx.x;
    if (idx >= NETYPES * NEDGE) return;
    int e = idx / NEDGE, j = idx % NEDGE;
    const int* base = ei + (size_t)e * 2 * NEDGE;
    int src = base[j];
    int dst = base[NEDGE + j];
    int pos = atomicAdd(&g_cur[e * NN + dst], 1);
    g_srcs[(size_t)e * NEDGE + pos] = src;
}

// ---------------- compose Wcat = [q_w | k_w@R_att | v_w@R_msg] ----------------
__global__ void compose_kernel(const float* __restrict__ kw, const float* __restrict__ kb,
                               const float* __restrict__ qw, const float* __restrict__ qb,
                               const float* __restrict__ vw, const float* __restrict__ vb,
                               const float* __restrict__ ratt, const float* __restrict__ rmsg,
                               int l) {
    int idx = blockIdx.x * blockDim.x + threadIdx.x;
    const int total = NTYPES * 384 * 129;
    if (idx >= total) return;
    int t = idx / (384 * 129);
    int r = idx % (384 * 129);
    int j = r / 129;
    int i = r % 129;
    float val;
    if (j < 128) {
        val = (i < 128) ? qw[(((size_t)l * NTYPES + t) * 128 + i) * 128 + j]
                        : qb[((size_t)l * NTYPES + t) * 128 + j];
    } else {
        bool isK = (j < 256);
        int jo = j - (isK ? 128 : 256);
        int hh = jo >> 5, eo = jo & 31;
        int e = 0;
        for (int ee = 0; ee < NETYPES; ee++) if (c_esrc[ee] == t) e = ee;
        const float* rel = (isK ? ratt : rmsg) +
                           ((((size_t)l * NETYPES + e) * NH + hh) * DH) * DH + eo;
        float s = 0.f;
        if (i < 128) {
            const float* wr = (isK ? kw : vw) + (((size_t)l * NTYPES + t) * 128 + i) * 128 + hh * 32;
            #pragma unroll
            for (int d = 0; d < 32; d++) s += wr[d] * rel[d * 32];
        } else {
            const float* br = (isK ? kb : vb) + ((size_t)l * NTYPES + t) * 128 + hh * 32;
            #pragma unroll
            for (int d = 0; d < 32; d++) s += br[d] * rel[d * 32];
        }
        val = s;
    }
    if (i < 128) g_wcat[((size_t)t * 128 + i) * 384 + j] = val;
    else         g_bcat[l][t * 384 + j] = val;
}

// ---------------- A split+pack: fp32 [z][NN][128] -> mma A-fragment images ----------------
__global__ void split_pack_kernel(const float* __restrict__ src,
                                  uint4* __restrict__ dhi, uint4* __restrict__ dlo) {
    int idx = blockIdx.x * blockDim.x + threadIdx.x;
    const int total = NTYPES * MTILES * 8 * 32;
    if (idx >= total) return;
    int lane = idx & 31;
    int s = (idx >> 5) & 7;
    int mt = (idx >> 8) % MTILES;
    int z = idx / (MTILES * 8 * 32);
    int g = lane >> 2, tig = lane & 3;
    int r0 = mt * 16 + g;
    int c0 = s * 16 + tig * 2;
    const float* S = src + (size_t)z * NN * 128;
    float2 p00 = *(const float2*)(S + (size_t)r0 * 128 + c0);
    float2 p10 = *(const float2*)(S + (size_t)(r0 + 8) * 128 + c0);
    float2 p01 = *(const float2*)(S + (size_t)r0 * 128 + c0 + 8);
    float2 p11 = *(const float2*)(S + (size_t)(r0 + 8) * 128 + c0 + 8);
    uint4 hi, lo;
    hi.x = split2(p00.x, p00.y, lo.x);
    hi.y = split2(p10.x, p10.y, lo.y);
    hi.z = split2(p01.x, p01.y, lo.z);
    hi.w = split2(p11.x, p11.y, lo.w);
    size_t o = (((size_t)z * MTILES + mt) * 8 + s) * 32 + lane;
    dhi[o] = hi;
    dlo[o] = lo;
}

// ---------------- B prep: fp32 W[k][n] -> fp16 B-fragment images (hi only) ----------------
__global__ void prep_b_kernel(const float* __restrict__ Wsrc, int Nout, int zstride, int imgBase) {
    int idx = blockIdx.x * blockDim.x + threadIdx.x;
    const int ntl = Nout >> 7;
    const int total = NTYPES * ntl * 8 * 16 * 32;
    if (idx >= total) return;
    int lane = idx & 31;
    int f = (idx >> 5) & 15;
    int s = (idx >> 9) & 7;
    int nt = (idx >> 12) % ntl;
    int z = idx / (ntl * 8 * 16 * 32);
    int g = lane >> 2, tig = lane & 3;
    int n = nt * 128 + f * 8 + g;
    int k0 = s * 16 + tig * 2;
    const float* W = Wsrc + (size_t)z * zstride;
    float w00 = W[(size_t)k0 * Nout + n];
    float w01 = W[(size_t)(k0 + 1) * Nout + n];
    float w10 = W[(size_t)(k0 + 8) * Nout + n];
    float w11 = W[(size_t)(k0 + 9) * Nout + n];
    uint32_t l0, l1;
    uint32_t h0 = split2(w00, w01, l0);
    uint32_t h1 = split2(w10, w11, l1);
    uint2* img = (uint2*)(g_bsplit + ((size_t)(imgBase + z * ntl + nt)) * 65536);
    img[(s * 16 + f) * 32 + lane] = make_uint2(h0, h1);
}

// ---------------- fp16 2-term mma GEMM: exact-A x fp16(B) ----------------
// epi: 0 none, 1 relu + edge-weight row scaling, 2 skip-gated residual.
// kvmode: C is a 1024B/row proj buffer; nt==0 -> q fp32, nt==1/2 -> k/v fp16.
__global__ void __launch_bounds__(256, 2)
gemm_mma(const uint4* __restrict__ Ahi, const uint4* __restrict__ Alo,
         const float* __restrict__ bias, int sB,
         float* C, size_t sC,
         const uint4* resHi, const uint4* resLo,
         const float* __restrict__ skipv,
         int Ntot, int epi, const float* __restrict__ ew,
         uint4* packHi, uint4* packLo, int imgBase, int zoff, int kvmode) {
    extern __shared__ uint2 Bs[];  // 4096 x 8B = 32KB
    const int z = zoff + blockIdx.z, nt = blockIdx.y;
    const int tid = threadIdx.x, warp = tid >> 5, lane = tid & 31;
    const int wm = warp >> 1, wn = warp & 1;
    const int g = lane >> 2, tig = lane & 3;
    const int ntl = gridDim.y;

    {
        const uint4* Bimg = (const uint4*)(g_bsplit + ((size_t)(imgBase + z * ntl + nt)) * 65536);
        uint4* Bs4 = (uint4*)Bs;
        #pragma unroll
        for (int i = 0; i < 8; i++) Bs4[tid + i * 256] = Bimg[tid + i * 256];
    }
    __syncthreads();

    const int mt0 = blockIdx.x * 8 + wm * 2;
    float acc[2][8][4];
    #pragma unroll
    for (int a = 0; a < 2; a++)
        #pragma unroll
        for (int b = 0; b < 8; b++)
            #pragma unroll
            for (int c = 0; c < 4; c++) acc[a][b][c] = 0.f;

    uint4 aH[2], aL[2], nHbuf[2], nLbuf[2];
    const uint4 zero4 = make_uint4(0, 0, 0, 0);
    #pragma unroll
    for (int mt = 0; mt < 2; mt++) {
        int mtg = mt0 + mt;
        if (mtg < MTILES) {
            size_t o = (((size_t)z * MTILES + mtg) * 8 + 0) * 32 + lane;
            aH[mt] = Ahi[o]; aL[mt] = Alo[o];
        } else { aH[mt] = zero4; aL[mt] = zero4; }
    }

    for (int s = 0; s < 8; s++) {
        if (s < 7) {
            #pragma unroll
            for (int mt = 0; mt < 2; mt++) {
                int mtg = mt0 + mt;
                if (mtg < MTILES) {
                    size_t o = (((size_t)z * MTILES + mtg) * 8 + (s + 1)) * 32 + lane;
                    nHbuf[mt] = Ahi[o]; nLbuf[mt] = Alo[o];
                } else { nHbuf[mt] = zero4; nLbuf[mt] = zero4; }
            }
        }
        #pragma unroll
        for (int f = 0; f < 8; f++) {
            uint2 q = Bs[(s * 16 + wn * 8 + f) * 32 + lane];
            #pragma unroll
            for (int mt = 0; mt < 2; mt++) {
                MMA_F16(acc[mt][f], aH[mt], q.x, q.y);   // ah*bh
                MMA_F16(acc[mt][f], aL[mt], q.x, q.y);   // al*bh
            }
        }
        #pragma unroll
        for (int mt = 0; mt < 2; mt++) { aH[mt] = nHbuf[mt]; aL[mt] = nLbuf[mt]; }
    }

    // ---- epilogue ----
    const float* biasz = bias + (size_t)z * sB;
    float* Cz = C ? C + (size_t)z * sC : nullptr;
    float beta = 1.f, omb = 0.f;
    if (epi == 2) {
        float sv = skipv[z];
        beta = 1.f / (1.f + expf(-sv));
        omb = 1.f - beta;
    }
    const int n0 = nt * 128 + wn * 64;
    #pragma unroll
    for (int mt = 0; mt < 2; mt++) {
        int mtg = mt0 + mt;
        if (mtg >= MTILES) continue;
        int r0 = mtg * 16 + g;
        float w0 = 1.f, w1 = 1.f;
        if (epi == 1) {
            int li0 = g_last[z * NN + r0];
            int li1 = g_last[z * NN + r0 + 8];
            if (li0 >= 0) w0 = 1.f / (1.f + expf(-ew[(size_t)z * NEDGE + li0]));
            if (li1 >= 0) w1 = 1.f / (1.f + expf(-ew[(size_t)z * NEDGE + li1]));
        }
        #pragma unroll
        for (int sl = 0; sl < 4; sl++) {
            int fe = sl * 2, fo = fe + 1;
            size_t o = (((size_t)z * MTILES + mtg) * 8 + (wn * 4 + sl)) * 32 + lane;
            float ve[4], vo[4];
            {
                int c = n0 + fe * 8 + tig * 2;
                float2 b2 = *(const float2*)(biasz + c);
                ve[0] = acc[mt][fe][0] + b2.x; ve[1] = acc[mt][fe][1] + b2.y;
                ve[2] = acc[mt][fe][2] + b2.x; ve[3] = acc[mt][fe][3] + b2.y;
            }
            {
                int c = n0 + fo * 8 + tig * 2;
                float2 b2 = *(const float2*)(biasz + c);
                vo[0] = acc[mt][fo][0] + b2.x; vo[1] = acc[mt][fo][1] + b2.y;
                vo[2] = acc[mt][fo][2] + b2.x; vo[3] = acc[mt][fo][3] + b2.y;
            }
            if (epi == 1) {
                #pragma unroll
                for (int i = 0; i < 4; i++) { ve[i] = fmaxf(ve[i], 0.f); vo[i] = fmaxf(vo[i], 0.f); }
                ve[0] *= w0; ve[1] *= w0; ve[2] *= w1; ve[3] *= w1;
                vo[0] *= w0; vo[1] *= w0; vo[2] *= w1; vo[3] *= w1;
            } else if (epi == 2) {
                uint4 rh = resHi[o], rl = resLo[o];
                float2 p0 = unsplit2(rh.x, rl.x);
                float2 p1 = unsplit2(rh.y, rl.y);
                float2 p2 = unsplit2(rh.z, rl.z);
                float2 p3 = unsplit2(rh.w, rl.w);
                ve[0] = beta * ve[0] + omb * p0.x; ve[1] = beta * ve[1] + omb * p0.y;
                ve[2] = beta * ve[2] + omb * p1.x; ve[3] = beta * ve[3] + omb * p1.y;
                vo[0] = beta * vo[0] + omb * p2.x; vo[1] = beta * vo[1] + omb * p2.y;
                vo[2] = beta * vo[2] + omb * p3.x; vo[3] = beta * vo[3] + omb * p3.y;
            }
            if (Cz) {
                if (!kvmode) {
                    int ce = n0 + fe * 8 + tig * 2, co = n0 + fo * 8 + tig * 2;
                    *(float2*)(Cz + (size_t)r0 * Ntot + ce)       = make_float2(ve[0], ve[1]);
                    *(float2*)(Cz + (size_t)(r0 + 8) * Ntot + ce) = make_float2(ve[2], ve[3]);
                    *(float2*)(Cz + (size_t)r0 * Ntot + co)       = make_float2(vo[0], vo[1]);
                    *(float2*)(Cz + (size_t)(r0 + 8) * Ntot + co) = make_float2(vo[2], vo[3]);
                } else {
                    int lce = wn * 64 + fe * 8 + tig * 2;
                    int lco = lce + 8;
                    char* rpa = (char*)Cz + (size_t)r0 * 1024;
                    char* rpb = (char*)Cz + (size_t)(r0 + 8) * 1024;
                    if (nt == 0) {
                        *(float2*)(rpa + lce * 4) = make_float2(ve[0], ve[1]);
                        *(float2*)(rpb + lce * 4) = make_float2(ve[2], ve[3]);
                        *(float2*)(rpa + lco * 4) = make_float2(vo[0], vo[1]);
                        *(float2*)(rpb + lco * 4) = make_float2(vo[2], vo[3]);
                    } else {
                        int off = 512 + (nt - 1) * 256;
                        *(__half2*)(rpa + off + lce * 2) = __floats2half2_rn(ve[0], ve[1]);
                        *(__half2*)(rpb + off + lce * 2) = __floats2half2_rn(ve[2], ve[3]);
                        *(__half2*)(rpa + off + lco * 2) = __floats2half2_rn(vo[0], vo[1]);
                        *(__half2*)(rpb + off + lco * 2) = __floats2half2_rn(vo[2], vo[3]);
                    }
                }
            }
            if (packHi) {
                uint4 hi, lo;
                hi.x = split2(ve[0], ve[1], lo.x);
                hi.y = split2(ve[2], ve[3], lo.y);
                hi.z = split2(vo[0], vo[1], lo.z);
                hi.w = split2(vo[2], vo[3], lo.w);
                packHi[o] = hi;
                packLo[o] = lo;
            }
        }
    }
}

// ---------------- attention + aggregation + gelu + pack, one edge type per launch ----------------
// proj row: 1024B = [q fp32 x128][k fp16 x128][v fp16 x128]
__global__ void __launch_bounds__(512)
attn_pack_kernel(const float* __restrict__ relp, int e,
                 uint4* __restrict__ dhi, uint4* __restrict__ dlo) {
    __shared__ float sO[16][132];
    int tid = threadIdx.x;
    int warp = tid >> 5, lane = tid & 31;
    int mt = blockIdx.x;
    int n = mt * 16 + warp;
    int t = c_edst[e], s = c_esrc[e];
    const char* projT = (const char*)g_proj + (size_t)t * NN * 1024;
    const char* projS = (const char*)g_proj + (size_t)s * NN * 1024;
    const int* offE = g_off + e * (NN + 1);
    const int* srcE = g_srcs + (size_t)e * NEDGE;
    int hg = lane >> 3;
    float ascale = relp[e * NH + hg] * 0.17677669529663689f;
    float4 q4 = *(const float4*)(projT + (size_t)n * 1024 + lane * 16);
    int beg = offE[n], end = offE[n + 1];
    float m = -3.0e38f, ssum = 0.f;
    float4 acc = make_float4(0.f, 0.f, 0.f, 0.f);
    int p2 = beg;
    for (; p2 + 2 <= end; p2 += 2) {
        int u0 = srcE[p2], u1 = srcE[p2 + 1];
        const char* rs0 = projS + (size_t)u0 * 1024;
        const char* rs1 = projS + (size_t)u1 * 1024;
        uint2 kr0 = *(const uint2*)(rs0 + 512 + lane * 8);
        uint2 vr0 = *(const uint2*)(rs0 + 768 + lane * 8);
        uint2 kr1 = *(const uint2*)(rs1 + 512 + lane * 8);
        uint2 vr1 = *(const uint2*)(rs1 + 768 + lane * 8);
        float2 k0a = __half22float2(*(__half2*)&kr0.x), k0b = __half22float2(*(__half2*)&kr0.y);
        float2 v0a = __half22float2(*(__half2*)&vr0.x), v0b = __half22float2(*(__half2*)&vr0.y);
        float2 k1a = __half22float2(*(__half2*)&kr1.x), k1b = __half22float2(*(__half2*)&kr1.y);
        float2 v1a = __half22float2(*(__half2*)&vr1.x), v1b = __half22float2(*(__half2*)&vr1.y);
        float d0 = q4.x * k0a.x + q4.y * k0a.y + q4.z * k0b.x + q4.w * k0b.y;
        float d1 = q4.x * k1a.x + q4.y * k1a.y + q4.z * k1b.x + q4.w * k1b.y;
        d0 += __shfl_xor_sync(0xffffffffu, d0, 1);
        d1 += __shfl_xor_sync(0xffffffffu, d1, 1);
        d0 += __shfl_xor_sync(0xffffffffu, d0, 2);
        d1 += __shfl_xor_sync(0xffffffffu, d1, 2);
        d0 += __shfl_xor_sync(0xffffffffu, d0, 4);
        d1 += __shfl_xor_sync(0xffffffffu, d1, 4);
        float a0 = d0 * ascale, a1 = d1 * ascale;
        float nm = fmaxf(m, fmaxf(a0, a1));
        float sc = __expf(m - nm);
        float pe0 = __expf(a0 - nm), pe1 = __expf(a1 - nm);
        ssum = ssum * sc + pe0 + pe1;
        acc.x = acc.x * sc + pe0 * v0a.x + pe1 * v1a.x;
        acc.y = acc.y * sc + pe0 * v0a.y + pe1 * v1a.y;
        acc.z = acc.z * sc + pe0 * v0b.x + pe1 * v1b.x;
        acc.w = acc.w * sc + pe0 * v0b.y + pe1 * v1b.y;
        m = nm;
    }
    for (; p2 < end; ++p2) {
        int u = srcE[p2];
        const char* rs = projS + (size_t)u * 1024;
        uint2 kr = *(const uint2*)(rs + 512 + lane * 8);
        uint2 vr = *(const uint2*)(rs + 768 + lane * 8);
        float2 ka = __half22float2(*(__half2*)&kr.x), kb = __half22float2(*(__half2*)&kr.y);
        float2 va = __half22float2(*(__half2*)&vr.x), vb = __half22float2(*(__half2*)&vr.y);
        float d = q4.x * ka.x + q4.y * ka.y + q4.z * kb.x + q4.w * kb.y;
        d += __shfl_xor_sync(0xffffffffu, d, 1);
        d += __shfl_xor_sync(0xffffffffu, d, 2);
        d += __shfl_xor_sync(0xffffffffu, d, 4);
        float a = d * ascale;
        float nm = fmaxf(m, a);
        float sc = __expf(m - nm), pe = __expf(a - nm);
        ssum = ssum * sc + pe;
        acc.x = acc.x * sc + pe * va.x;
        acc.y = acc.y * sc + pe * va.y;
        acc.z = acc.z * sc + pe * vb.x;
        acc.w = acc.w * sc + pe * vb.y;
        m = nm;
    }
    float inv = 1.f / (ssum + 1e-16f);
    int cb = lane * 4;
    sO[warp][cb + 0] = acc.x * inv;
    sO[warp][cb + 1] = acc.y * inv;
    sO[warp][cb + 2] = acc.z * inv;
    sO[warp][cb + 3] = acc.w * inv;
    __syncthreads();

    if (tid < 256) {
        int sstep = tid >> 5, ln = tid & 31;
        int g = ln >> 2, tig = ln & 3;
        int c0 = sstep * 16 + tig * 2;
        float p00x = gelu_exact(sO[g][c0]);
        float p00y = gelu_exact(sO[g][c0 + 1]);
        float p10x = gelu_exact(sO[g + 8][c0]);
        float p10y = gelu_exact(sO[g + 8][c0 + 1]);
        float p01x = gelu_exact(sO[g][c0 + 8]);
        float p01y = gelu_exact(sO[g][c0 + 9]);
        float p11x = gelu_exact(sO[g + 8][c0 + 8]);
        float p11y = gelu_exact(sO[g + 8][c0 + 9]);
        uint4 hi, lo;
        hi.x = split2(p00x, p00y, lo.x);
        hi.y = split2(p10x, p10y, lo.y);
        hi.z = split2(p01x, p01y, lo.z);
        hi.w = split2(p11x, p11y, lo.w);
        size_t o = (((size_t)t * MTILES + mt) * 8 + sstep) * 32 + ln;
        dhi[o] = hi;
        dlo[o] = lo;
    }
}

// ---------------- launch ----------------
extern "C" void kernel_launch(void* const* d_in, const int* in_sizes, int n_in,
                              void* d_out, int out_size) {
    const float* x       = (const float*)d_in[0];
    const int*   ei      = (const int*)  d_in[1];
    const float* ew      = (const float*)d_in[2];
    const float* lin_w   = (const float*)d_in[3];
    const float* lin_b   = (const float*)d_in[4];
    const float* k_w     = (const float*)d_in[5];
    const float* k_b     = (const float*)d_in[6];
    const float* q_w     = (const float*)d_in[7];
    const float* q_b     = (const float*)d_in[8];
    const float* v_w     = (const float*)d_in[9];
    const float* v_b     = (const float*)d_in[10];
    const float* a_w     = (const float*)d_in[11];
    const float* a_b     = (const float*)d_in[12];
    const float* skip    = (const float*)d_in[13];
    const float* rel_att = (const float*)d_in[14];
    const float* rel_msg = (const float*)d_in[15];
    const float* rel_p   = (const float*)d_in[16];
    float* out = (float*)d_out;

    float *pproj, *pwcat, *pbcat;
    uint4 *pAh, *pAl, *pHh, *pHl;
    cudaGetSymbolAddress((void**)&pproj, g_proj);
    cudaGetSymbolAddress((void**)&pwcat, g_wcat);
    cudaGetSymbolAddress((void**)&pbcat, g_bcat);
    cudaGetSymbolAddress((void**)&pAh,   g_pkA_hi);
    cudaGetSymbolAddress((void**)&pAl,   g_pkA_lo);
    cudaGetSymbolAddress((void**)&pHh,   g_pkH_hi);
    cudaGetSymbolAddress((void**)&pHl,   g_pkH_lo);

    static int inited = 0;
    static cudaStream_t s2, s3;
    static cudaEvent_t evFork, evA, evB, evCnt, evCSR, evQKV, evAt0, evAt1, evOut1;
    const int SMEM_GEMM = 32768;
    if (!inited) {
        cudaFuncSetAttribute(gemm_mma, cudaFuncAttributeMaxDynamicSharedMemorySize, SMEM_GEMM);
        cudaStreamCreateWithFlags(&s2, cudaStreamNonBlocking);
        cudaStreamCreateWithFlags(&s3, cudaStreamNonBlocking);
        cudaEventCreateWithFlags(&evFork, cudaEventDisableTiming);
        cudaEventCreateWithFlags(&evA, cudaEventDisableTiming);
        cudaEventCreateWithFlags(&evB, cudaEventDisableTiming);
        cudaEventCreateWithFlags(&evCnt, cudaEventDisableTiming);
        cudaEventCreateWithFlags(&evCSR, cudaEventDisableTiming);
        cudaEventCreateWithFlags(&evQKV, cudaEventDisableTiming);
        cudaEventCreateWithFlags(&evAt0, cudaEventDisableTiming);
        cudaEventCreateWithFlags(&evAt1, cudaEventDisableTiming);
        cudaEventCreateWithFlags(&evOut1, cudaEventDisableTiming);
        inited = 1;
    }

    const int MB = (NN + 127) / 128;  // 391
    const int PACK_T = NTYPES * MTILES * 8 * 32;

    // ---- fork: weight-side prep on s2, CSR on main / s3 ----
    cudaEventRecord(evFork, 0);
    cudaStreamWaitEvent(s2, evFork, 0);

    // s2: independent prep chain
    split_pack_kernel<<<(PACK_T + 255) / 256, 256, 0, s2>>>(x, pAh, pAl);
    prep_b_kernel<<<(NTYPES * 4096 + 255) / 256, 256, 0, s2>>>(lin_w, 128, 128 * 128, 0);
    cudaEventRecord(evA, s2);
    compose_kernel<<<(NTYPES * 384 * 129 + 255) / 256, 256, 0, s2>>>(
        k_w, k_b, q_w, q_b, v_w, v_b, rel_att, rel_msg, 0);
    prep_b_kernel<<<(NTYPES * 3 * 4096 + 255) / 256, 256, 0, s2>>>(pwcat, 384, 128 * 384, 2);
    prep_b_kernel<<<(NTYPES * 4096 + 255) / 256, 256, 0, s2>>>(a_w, 128, 128 * 128, 8);
    compose_kernel<<<(NTYPES * 384 * 129 + 255) / 256, 256, 0, s2>>>(
        k_w, k_b, q_w, q_b, v_w, v_b, rel_att, rel_msg, 1);
    prep_b_kernel<<<(NTYPES * 3 * 4096 + 255) / 256, 256, 0, s2>>>(pwcat, 384, 128 * 384, 10);
    prep_b_kernel<<<(NTYPES * 4096 + 255) / 256, 256, 0, s2>>>(
        a_w + (size_t)NTYPES * 128 * 128, 128, 128 * 128, 16);
    cudaEventRecord(evB, s2);

    // main: init + count (input-proj epilogue needs only g_last)
    init_kernel<<<(NETYPES * NN + 255) / 256, 256>>>();
    edge_count_kernel<<<(NETYPES * NEDGE + 255) / 256, 256>>>(ei);
    cudaEventRecord(evCnt, 0);

    // s3: scan + scatter concurrent with input GEMM
    cudaStreamWaitEvent(s3, evCnt, 0);
    scan_kernel<<<NETYPES, 1024, 0, s3>>>();
    edge_scatter_kernel<<<(NETYPES * NEDGE + 255) / 256, 256, 0, s3>>>(ei);
    cudaEventRecord(evCSR, s3);

    // input projection + relu + edge-weight scaling -> packed H only
    cudaStreamWaitEvent(0, evA, 0);
    gemm_mma<<<dim3(MB, 1, NTYPES), 256, SMEM_GEMM>>>(
        pAh, pAl, lin_b, 128, nullptr, 0, nullptr, nullptr, nullptr,
        128, 1, ew, pHh, pHl, 0, 0, 0);

    cudaStreamWaitEvent(0, evB, 0);
    cudaStreamWaitEvent(0, evCSR, 0);

    for (int l = 0; l < NL; l++) {
        bool last = (l == NL - 1);

        // fused q | k | v projection (both types), kv stored fp16
        gemm_mma<<<dim3(MB, 3, NTYPES), 256, SMEM_GEMM>>>(
            pHh, pHl, pbcat + l * NTYPES * 384, 384, pproj, (size_t)NN * 256,
            nullptr, nullptr, nullptr, 384, 0, nullptr, nullptr, nullptr, 2 + l * 8, 0, 1);
        cudaEventRecord(evQKV, 0);

        // main: attn e=0 -> packed A for t=1
        attn_pack_kernel<<<MTILES, 512>>>(rel_p + l * NETYPES * NH, 0, pAh, pAl);
        cudaEventRecord(evAt0, 0);

        // s2: attn e=1 (concurrent with attn e=0) -> packed A for t=0
        cudaStreamWaitEvent(s2, evQKV, 0);
        attn_pack_kernel<<<MTILES, 512, 0, s2>>>(rel_p + l * NETYPES * NH, 1, pAh, pAl);
        cudaEventRecord(evAt1, s2);

        // s2: out-proj z=1 (needs attn e=0's output; in-order after attn e=1 on s2)
        cudaStreamWaitEvent(s2, evAt0, 0);
        gemm_mma<<<dim3(MB, 1, 1), 256, SMEM_GEMM, s2>>>(
            pAh, pAl, a_b + (size_t)l * NTYPES * 128, 128,
            last ? out : nullptr, (size_t)NN * 128,
            pHh, pHl, skip + l * NTYPES, 128, 2, nullptr,
            last ? nullptr : pHh, last ? nullptr : pHl, 8 + l * 8, 1, 0);
        cudaEventRecord(evOut1, s2);

        // main: out-proj z=0 (needs attn e=1's output)
        cudaStreamWaitEvent(0, evAt1, 0);
        gemm_mma<<<dim3(MB, 1, 1), 256, SMEM_GEMM>>>(
            pAh, pAl, a_b + (size_t)l * NTYPES * 128, 128,
            last ? out : nullptr, (size_t)NN * 128,
            pHh, pHl, skip + l * NTYPES, 128, 2, nullptr,
            last ? nullptr : pHh, last ? nullptr : pHl, 8 + l * 8, 0, 0);

        // join z=1 out-proj before next layer (or before finishing)
        cudaStreamWaitEvent(0, evOut1, 0);
    }
}